// round 2
// baseline (speedup 1.0000x reference)
#include <cuda_runtime.h>
#include <math.h>

#define Bb 2
#define Tt 2048
#define Ss 2048
#define Hh 16
#define Dd 64
#define Ee 1024

// Scratch (static __device__ — allocation-free per harness rules)
__device__ float g_qp[(size_t)Bb * Hh * Tt * Dd];   // (B,H,T,D)
__device__ float g_kp[(size_t)Bb * Hh * Ss * Dd];   // (B,H,S,D)
__device__ float g_vp[(size_t)Bb * Hh * Ss * Dd];   // (B,H,S,D)
__device__ float g_attn[(size_t)Bb * Hh * Tt * Ss]; // (B,H,T,S)  512 MB
__device__ float g_ctx[(size_t)Bb * Tt * Ee];       // (B,T,E)

// ---------------------------------------------------------------------------
// Kernel 1: fused QKV projection.  z = 0/1/2 selects q/k/v.
// out[((b*H+h)*T + t)*D + d] = sum_e A[m,e] * w[n,e] + bias[n]
// 64x64 tile, BK=16, 256 threads, 4x4 micro-tile.
// ---------------------------------------------------------------------------
__global__ __launch_bounds__(256)
void proj_kernel(const float* __restrict__ q,
                 const float* __restrict__ kv,
                 const float* __restrict__ w_all,
                 const float* __restrict__ b_all)
{
    const int z = blockIdx.z;
    const float* A;
    int lda;
    float* out;
    if (z == 0)      { A = q;        lda = Ee;     out = g_qp; }
    else if (z == 1) { A = kv;       lda = 2 * Ee; out = g_kp; }
    else             { A = kv + Ee;  lda = 2 * Ee; out = g_vp; }
    const float* w    = w_all + (size_t)z * Ee * Ee;
    const float* bias = b_all + z * Ee;

    __shared__ float As[16][65];
    __shared__ float Bs[16][65];

    const int tx = threadIdx.x, ty = threadIdx.y;
    const int tid = ty * 16 + tx;
    const int row0 = blockIdx.y * 64;
    const int col0 = blockIdx.x * 64;

    const int lr = tid >> 2;       // 0..63
    const int lc = (tid & 3) * 4;  // 0,4,8,12

    float acc[4][4];
#pragma unroll
    for (int i = 0; i < 4; i++)
#pragma unroll
        for (int j = 0; j < 4; j++) acc[i][j] = 0.0f;

    for (int k0 = 0; k0 < Ee; k0 += 16) {
        float4 av = *reinterpret_cast<const float4*>(
            &A[(size_t)(row0 + lr) * lda + k0 + lc]);
        As[lc + 0][lr] = av.x; As[lc + 1][lr] = av.y;
        As[lc + 2][lr] = av.z; As[lc + 3][lr] = av.w;
        float4 bv = *reinterpret_cast<const float4*>(
            &w[(size_t)(col0 + lr) * Ee + k0 + lc]);
        Bs[lc + 0][lr] = bv.x; Bs[lc + 1][lr] = bv.y;
        Bs[lc + 2][lr] = bv.z; Bs[lc + 3][lr] = bv.w;
        __syncthreads();
#pragma unroll
        for (int kk = 0; kk < 16; kk++) {
            float a[4], bvv[4];
#pragma unroll
            for (int i = 0; i < 4; i++) a[i] = As[kk][ty * 4 + i];
#pragma unroll
            for (int j = 0; j < 4; j++) bvv[j] = Bs[kk][tx * 4 + j];
#pragma unroll
            for (int i = 0; i < 4; i++)
#pragma unroll
                for (int j = 0; j < 4; j++)
                    acc[i][j] = fmaf(a[i], bvv[j], acc[i][j]);
        }
        __syncthreads();
    }

#pragma unroll
    for (int i = 0; i < 4; i++) {
        const int m = row0 + ty * 4 + i;
        const int b = m / Tt, t = m % Tt;
#pragma unroll
        for (int j = 0; j < 4; j++) {
            const int n = col0 + tx * 4 + j;
            const int h = n >> 6, d = n & 63;
            out[(((size_t)b * Hh + h) * Tt + t) * Dd + d] = acc[i][j] + bias[n];
        }
    }
}

// ---------------------------------------------------------------------------
// Kernel 2: scores = scale * qp @ kp^T, per (b,h).  M=N=2048, K=64.
// ---------------------------------------------------------------------------
__global__ __launch_bounds__(256)
void scores_kernel()
{
    const int bh = blockIdx.z;
    const float* A  = g_qp + (size_t)bh * Tt * Dd;  // [T][64]
    const float* Bp = g_kp + (size_t)bh * Ss * Dd;  // [S][64]
    float* C = g_attn + (size_t)bh * Tt * Ss;

    __shared__ float As[16][65];
    __shared__ float Bs[16][65];

    const int tx = threadIdx.x, ty = threadIdx.y;
    const int tid = ty * 16 + tx;
    const int row0 = blockIdx.y * 64;
    const int col0 = blockIdx.x * 64;
    const int lr = tid >> 2;
    const int lc = (tid & 3) * 4;

    float acc[4][4];
#pragma unroll
    for (int i = 0; i < 4; i++)
#pragma unroll
        for (int j = 0; j < 4; j++) acc[i][j] = 0.0f;

    for (int k0 = 0; k0 < Dd; k0 += 16) {
        float4 av = *reinterpret_cast<const float4*>(
            &A[(size_t)(row0 + lr) * Dd + k0 + lc]);
        As[lc + 0][lr] = av.x; As[lc + 1][lr] = av.y;
        As[lc + 2][lr] = av.z; As[lc + 3][lr] = av.w;
        float4 bv = *reinterpret_cast<const float4*>(
            &Bp[(size_t)(col0 + lr) * Dd + k0 + lc]);
        Bs[lc + 0][lr] = bv.x; Bs[lc + 1][lr] = bv.y;
        Bs[lc + 2][lr] = bv.z; Bs[lc + 3][lr] = bv.w;
        __syncthreads();
#pragma unroll
        for (int kk = 0; kk < 16; kk++) {
            float a[4], bvv[4];
#pragma unroll
            for (int i = 0; i < 4; i++) a[i] = As[kk][ty * 4 + i];
#pragma unroll
            for (int j = 0; j < 4; j++) bvv[j] = Bs[kk][tx * 4 + j];
#pragma unroll
            for (int i = 0; i < 4; i++)
#pragma unroll
                for (int j = 0; j < 4; j++)
                    acc[i][j] = fmaf(a[i], bvv[j], acc[i][j]);
        }
        __syncthreads();
    }

    const float scale = 0.125f;  // 1/sqrt(64)
#pragma unroll
    for (int i = 0; i < 4; i++) {
        const int m = row0 + ty * 4 + i;
#pragma unroll
        for (int j = 0; j < 4; j++) {
            const int n = col0 + tx * 4 + j;
            C[(size_t)m * Ss + n] = acc[i][j] * scale;
        }
    }
}

// ---------------------------------------------------------------------------
// Kernel 3: softmax in place over s, per (b,t) CTA looping all 16 heads,
// accumulating head-mean into wout (second output region) in registers.
// ---------------------------------------------------------------------------
__global__ __launch_bounds__(256)
void softmax_kernel(float* __restrict__ wout)
{
    const int bt = blockIdx.x;           // b*T + t
    const int b = bt / Tt, t = bt % Tt;
    const int tid = threadIdx.x;         // 256 threads

    __shared__ float red[256];

    float wsum[8];
#pragma unroll
    for (int i = 0; i < 8; i++) wsum[i] = 0.0f;

    for (int h = 0; h < Hh; h++) {
        float* arow = g_attn + (((size_t)b * Hh + h) * Tt + t) * Ss;
        float lv[8];
        float lmax = -1e30f;
#pragma unroll
        for (int i = 0; i < 8; i++) {
            lv[i] = arow[tid + i * 256];
            lmax = fmaxf(lmax, lv[i]);
        }
        red[tid] = lmax;
        __syncthreads();
        for (int s = 128; s > 0; s >>= 1) {
            if (tid < s) red[tid] = fmaxf(red[tid], red[tid + s]);
            __syncthreads();
        }
        const float m = red[0];
        __syncthreads();
        float lsum = 0.0f;
#pragma unroll
        for (int i = 0; i < 8; i++) {
            lv[i] = __expf(lv[i] - m);
            lsum += lv[i];
        }
        red[tid] = lsum;
        __syncthreads();
        for (int s = 128; s > 0; s >>= 1) {
            if (tid < s) red[tid] += red[tid + s];
            __syncthreads();
        }
        const float inv = 1.0f / red[0];
        __syncthreads();
#pragma unroll
        for (int i = 0; i < 8; i++) {
            const float p = lv[i] * inv;
            arow[tid + i * 256] = p;
            wsum[i] += p * (1.0f / Hh);
        }
    }
#pragma unroll
    for (int i = 0; i < 8; i++)
        wout[(size_t)bt * Ss + tid + i * 256] = wsum[i];
}

// ---------------------------------------------------------------------------
// Kernel 4: ctx = attn @ vp, per (b,h).  M=2048, N=64, K=2048.
// Output scattered to (B,T,E) with column offset h*64.
// ---------------------------------------------------------------------------
__global__ __launch_bounds__(256)
void ctx_kernel()
{
    const int bh = blockIdx.z;
    const int b = bh / Hh, h = bh % Hh;
    const float* A  = g_attn + (size_t)bh * Tt * Ss;  // [T][S]
    const float* Vp = g_vp   + (size_t)bh * Ss * Dd;  // [S][64], K-major

    __shared__ float As[16][65];
    __shared__ float Bs[16][65];

    const int tx = threadIdx.x, ty = threadIdx.y;
    const int tid = ty * 16 + tx;
    const int row0 = blockIdx.y * 64;
    const int lr = tid >> 2;
    const int lc = (tid & 3) * 4;
    const int bkk = tid >> 4;        // 0..15
    const int bn4 = (tid & 15) * 4;  // 0..60

    float acc[4][4];
#pragma unroll
    for (int i = 0; i < 4; i++)
#pragma unroll
        for (int j = 0; j < 4; j++) acc[i][j] = 0.0f;

    for (int k0 = 0; k0 < Ss; k0 += 16) {
        float4 av = *reinterpret_cast<const float4*>(
            &A[(size_t)(row0 + lr) * Ss + k0 + lc]);
        As[lc + 0][lr] = av.x; As[lc + 1][lr] = av.y;
        As[lc + 2][lr] = av.z; As[lc + 3][lr] = av.w;
        // B is already K-major: Bs[kk][n] = Vp[(k0+kk)*64 + n]
        float4 bv = *reinterpret_cast<const float4*>(
            &Vp[(size_t)(k0 + bkk) * Dd + bn4]);
        Bs[bkk][bn4 + 0] = bv.x; Bs[bkk][bn4 + 1] = bv.y;
        Bs[bkk][bn4 + 2] = bv.z; Bs[bkk][bn4 + 3] = bv.w;
        __syncthreads();
#pragma unroll
        for (int kk = 0; kk < 16; kk++) {
            float a[4], bvv[4];
#pragma unroll
            for (int i = 0; i < 4; i++) a[i] = As[kk][ty * 4 + i];
#pragma unroll
            for (int j = 0; j < 4; j++) bvv[j] = Bs[kk][tx * 4 + j];
#pragma unroll
            for (int i = 0; i < 4; i++)
#pragma unroll
                for (int j = 0; j < 4; j++)
                    acc[i][j] = fmaf(a[i], bvv[j], acc[i][j]);
        }
        __syncthreads();
    }

#pragma unroll
    for (int i = 0; i < 4; i++) {
        const int t = row0 + ty * 4 + i;
#pragma unroll
        for (int j = 0; j < 4; j++) {
            const int d = tx * 4 + j;  // col0 == 0 (N == 64)
            g_ctx[((size_t)b * Tt + t) * Ee + h * Dd + d] = acc[i][j];
        }
    }
}

// ---------------------------------------------------------------------------
// Kernel 5: out = ctx @ out_proj_w^T + bias, straight into d_out (B*T, E).
// ---------------------------------------------------------------------------
__global__ __launch_bounds__(256)
void outproj_kernel(const float* __restrict__ w,
                    const float* __restrict__ bias,
                    float* __restrict__ out)
{
    __shared__ float As[16][65];
    __shared__ float Bs[16][65];

    const int tx = threadIdx.x, ty = threadIdx.y;
    const int tid = ty * 16 + tx;
    const int row0 = blockIdx.y * 64;
    const int col0 = blockIdx.x * 64;
    const int lr = tid >> 2;
    const int lc = (tid & 3) * 4;

    float acc[4][4];
#pragma unroll
    for (int i = 0; i < 4; i++)
#pragma unroll
        for (int j = 0; j < 4; j++) acc[i][j] = 0.0f;

    for (int k0 = 0; k0 < Ee; k0 += 16) {
        float4 av = *reinterpret_cast<const float4*>(
            &g_ctx[(size_t)(row0 + lr) * Ee + k0 + lc]);
        As[lc + 0][lr] = av.x; As[lc + 1][lr] = av.y;
        As[lc + 2][lr] = av.z; As[lc + 3][lr] = av.w;
        float4 bv = *reinterpret_cast<const float4*>(
            &w[(size_t)(col0 + lr) * Ee + k0 + lc]);
        Bs[lc + 0][lr] = bv.x; Bs[lc + 1][lr] = bv.y;
        Bs[lc + 2][lr] = bv.z; Bs[lc + 3][lr] = bv.w;
        __syncthreads();
#pragma unroll
        for (int kk = 0; kk < 16; kk++) {
            float a[4], bvv[4];
#pragma unroll
            for (int i = 0; i < 4; i++) a[i] = As[kk][ty * 4 + i];
#pragma unroll
            for (int j = 0; j < 4; j++) bvv[j] = Bs[kk][tx * 4 + j];
#pragma unroll
            for (int i = 0; i < 4; i++)
#pragma unroll
                for (int j = 0; j < 4; j++)
                    acc[i][j] = fmaf(a[i], bvv[j], acc[i][j]);
        }
        __syncthreads();
    }

#pragma unroll
    for (int i = 0; i < 4; i++) {
        const int m = row0 + ty * 4 + i;
#pragma unroll
        for (int j = 0; j < 4; j++) {
            const int n = col0 + tx * 4 + j;
            out[(size_t)m * Ee + n] = acc[i][j] + bias[n];
        }
    }
}

// ---------------------------------------------------------------------------
extern "C" void kernel_launch(void* const* d_in, const int* in_sizes, int n_in,
                              void* d_out, int out_size)
{
    const float* q    = (const float*)d_in[0];
    const float* kv   = (const float*)d_in[1];
    const float* ipw  = (const float*)d_in[2];
    const float* ipb  = (const float*)d_in[3];
    const float* opw  = (const float*)d_in[4];
    const float* opb  = (const float*)d_in[5];
    float* out = (float*)d_out;                       // (B,T,H,D) flattened
    float* wout = out + (size_t)Bb * Tt * Ee;         // (B,T,S) flattened

    dim3 thr(16, 16);

    // 1. QKV projections
    proj_kernel<<<dim3(Ee / 64, (Bb * Tt) / 64, 3), thr>>>(q, kv, ipw, ipb);

    // 2. scores
    scores_kernel<<<dim3(Ss / 64, Tt / 64, Bb * Hh), thr>>>();

    // 3. softmax + head-mean weights
    softmax_kernel<<<Bb * Tt, 256>>>(wout);

    // 4. ctx = attn @ V
    ctx_kernel<<<dim3(1, Tt / 64, Bb * Hh), thr>>>();

    // 5. out projection
    outproj_kernel<<<dim3(Ee / 64, (Bb * Tt) / 64), thr>>>(opw, opb, out);
}

// round 9
// speedup vs baseline: 1.4175x; 1.4175x over previous
#include <cuda_runtime.h>
#include <cuda_bf16.h>
#include <cstdint>
#include <math.h>

#define Bb 2
#define Tt 2048
#define Ss 2048
#define Hh 16
#define Dd 64
#define Ee 1024

// ---------------------------------------------------------------------------
// Scratch (static __device__ — allocation-free per harness rules)
// ---------------------------------------------------------------------------
__device__ float g_qp[(size_t)Bb * Hh * Tt * Dd];   // (B,H,T,D)
__device__ float g_kp[(size_t)Bb * Hh * Ss * Dd];   // (B,H,S,D)
__device__ float g_vp[(size_t)Bb * Hh * Ss * Dd];   // (B,H,S,D)
__device__ float g_attn[(size_t)Bb * Hh * Tt * Ss]; // (B,H,T,S)  512 MB
__device__ float g_ctx[(size_t)Bb * Tt * Ee];       // (B,T,E)

#define PROJ_ELEMS ((size_t)Bb * Hh * Tt * Dd)
__device__ __nv_bfloat16 g_qhi[PROJ_ELEMS], g_qlo[PROJ_ELEMS];
__device__ __nv_bfloat16 g_khi[PROJ_ELEMS], g_klo[PROJ_ELEMS];

// ---------------------------------------------------------------------------
// Warp MMA primitives (baseline sm_80+ PTX — compiles for plain sm_103)
// ---------------------------------------------------------------------------
__device__ __forceinline__ uint32_t smem_u32(const void* p) {
    uint32_t a;
    asm("{ .reg .u64 t; cvta.to.shared.u64 t, %1; cvt.u32.u64 %0, t; }"
        : "=r"(a) : "l"(p));
    return a;
}

__device__ __forceinline__ void mma16816(float* d, const uint32_t* a, const uint32_t* b) {
    asm volatile(
        "mma.sync.aligned.m16n8k16.row.col.f32.bf16.bf16.f32 "
        "{%0,%1,%2,%3}, {%4,%5,%6,%7}, {%8,%9}, {%0,%1,%2,%3};"
        : "+f"(d[0]), "+f"(d[1]), "+f"(d[2]), "+f"(d[3])
        : "r"(a[0]), "r"(a[1]), "r"(a[2]), "r"(a[3]), "r"(b[0]), "r"(b[1]));
}

#define LDSM4(R0,R1,R2,R3,ADDR) \
    asm volatile("ldmatrix.sync.aligned.m8n8.x4.shared.b16 {%0,%1,%2,%3}, [%4];" \
        : "=r"(R0),"=r"(R1),"=r"(R2),"=r"(R3) : "r"(ADDR))
#define LDSM4T(R0,R1,R2,R3,ADDR) \
    asm volatile("ldmatrix.sync.aligned.m8n8.x4.trans.shared.b16 {%0,%1,%2,%3}, [%4];" \
        : "=r"(R0),"=r"(R1),"=r"(R2),"=r"(R3) : "r"(ADDR))

// A-fragment (16x16 row-major tile in smem, row stride lds halfs)
__device__ __forceinline__ void load_a_frag(uint32_t* fr, uint32_t base_u32,
                                            int mbase, int ks, int lane, int lds) {
    const int row = mbase + (lane & 15);
    const int col = ks + ((lane >> 4) << 3);
    LDSM4(fr[0], fr[1], fr[2], fr[3], base_u32 + (uint32_t)(row * lds + col) * 2u);
}
// B-fragments for 2 n-tiles (16n x 16k) from [n][k] row-major smem
__device__ __forceinline__ void load_b_frag2(uint32_t* f0, uint32_t* f1, uint32_t base_u32,
                                             int nb, int ks, int lane, int lds) {
    const int g = lane >> 3, r = lane & 7;
    const int row = nb + ((g >> 1) << 3) + r;
    const int col = ks + ((g & 1) << 3);
    LDSM4(f0[0], f0[1], f1[0], f1[1], base_u32 + (uint32_t)(row * lds + col) * 2u);
}
// B-fragments for 2 n-tiles from [k][n] smem via trans
__device__ __forceinline__ void load_b_frag2_trans(uint32_t* f0, uint32_t* f1, uint32_t base_u32,
                                                   int db, int ks, int lane, int lds) {
    const int g = lane >> 3, r = lane & 7;
    const int row = ks + ((g & 1) << 3) + r;
    const int col = db + ((g >> 1) << 3);
    LDSM4T(f0[0], f0[1], f1[0], f1[1], base_u32 + (uint32_t)(row * lds + col) * 2u);
}

__device__ __forceinline__ void split4(float4 v, ushort4& hs, ushort4& ls)
{
    __nv_bfloat16 h0 = __float2bfloat16(v.x);
    __nv_bfloat16 h1 = __float2bfloat16(v.y);
    __nv_bfloat16 h2 = __float2bfloat16(v.z);
    __nv_bfloat16 h3 = __float2bfloat16(v.w);
    __nv_bfloat16 l0 = __float2bfloat16(v.x - __bfloat162float(h0));
    __nv_bfloat16 l1 = __float2bfloat16(v.y - __bfloat162float(h1));
    __nv_bfloat16 l2 = __float2bfloat16(v.z - __bfloat162float(h2));
    __nv_bfloat16 l3 = __float2bfloat16(v.w - __bfloat162float(h3));
    hs = make_ushort4(__bfloat16_as_ushort(h0), __bfloat16_as_ushort(h1),
                      __bfloat16_as_ushort(h2), __bfloat16_as_ushort(h3));
    ls = make_ushort4(__bfloat16_as_ushort(l0), __bfloat16_as_ushort(l1),
                      __bfloat16_as_ushort(l2), __bfloat16_as_ushort(l3));
}

// ---------------------------------------------------------------------------
// Kernel 1: fused QKV projection (fp32 FFMA — identical to R2-passing code)
// ---------------------------------------------------------------------------
__global__ __launch_bounds__(256)
void proj_kernel(const float* __restrict__ q,
                 const float* __restrict__ kv,
                 const float* __restrict__ w_all,
                 const float* __restrict__ b_all)
{
    const int z = blockIdx.z;
    const float* A;
    int lda;
    float* out;
    if (z == 0)      { A = q;        lda = Ee;     out = g_qp; }
    else if (z == 1) { A = kv;       lda = 2 * Ee; out = g_kp; }
    else             { A = kv + Ee;  lda = 2 * Ee; out = g_vp; }
    const float* w    = w_all + (size_t)z * Ee * Ee;
    const float* bias = b_all + z * Ee;

    __shared__ float As[16][65];
    __shared__ float Bs[16][65];

    const int tx = threadIdx.x, ty = threadIdx.y;
    const int tid = ty * 16 + tx;
    const int row0 = blockIdx.y * 64;
    const int col0 = blockIdx.x * 64;

    const int lr = tid >> 2;
    const int lc = (tid & 3) * 4;

    float acc[4][4];
#pragma unroll
    for (int i = 0; i < 4; i++)
#pragma unroll
        for (int j = 0; j < 4; j++) acc[i][j] = 0.0f;

    for (int k0 = 0; k0 < Ee; k0 += 16) {
        float4 av = *reinterpret_cast<const float4*>(
            &A[(size_t)(row0 + lr) * lda + k0 + lc]);
        As[lc + 0][lr] = av.x; As[lc + 1][lr] = av.y;
        As[lc + 2][lr] = av.z; As[lc + 3][lr] = av.w;
        float4 bv = *reinterpret_cast<const float4*>(
            &w[(size_t)(col0 + lr) * Ee + k0 + lc]);
        Bs[lc + 0][lr] = bv.x; Bs[lc + 1][lr] = bv.y;
        Bs[lc + 2][lr] = bv.z; Bs[lc + 3][lr] = bv.w;
        __syncthreads();
#pragma unroll
        for (int kk = 0; kk < 16; kk++) {
            float a[4], bvv[4];
#pragma unroll
            for (int i = 0; i < 4; i++) a[i] = As[kk][ty * 4 + i];
#pragma unroll
            for (int j = 0; j < 4; j++) bvv[j] = Bs[kk][tx * 4 + j];
#pragma unroll
            for (int i = 0; i < 4; i++)
#pragma unroll
                for (int j = 0; j < 4; j++)
                    acc[i][j] = fmaf(a[i], bvv[j], acc[i][j]);
        }
        __syncthreads();
    }

#pragma unroll
    for (int i = 0; i < 4; i++) {
        const int m = row0 + ty * 4 + i;
        const int b = m / Tt, t = m % Tt;
#pragma unroll
        for (int j = 0; j < 4; j++) {
            const int n = col0 + tx * 4 + j;
            const int h = n >> 6, d = n & 63;
            out[(((size_t)b * Hh + h) * Tt + t) * Dd + d] = acc[i][j] + bias[n];
        }
    }
}

// ---------------------------------------------------------------------------
// Kernel 1b: split q/k fp32 -> bf16 hi/lo
// ---------------------------------------------------------------------------
__global__ __launch_bounds__(256)
void convert_qk_kernel()
{
    const int z = blockIdx.z;
    const size_t idx4 = ((size_t)blockIdx.x * 256 + threadIdx.x) * 4;
    const float* src = (z == 0) ? g_qp : g_kp;
    __nv_bfloat16* dh = (z == 0) ? g_qhi : g_khi;
    __nv_bfloat16* dl = (z == 0) ? g_qlo : g_klo;
    float4 v = *reinterpret_cast<const float4*>(&src[idx4]);
    ushort4 hs, ls;
    split4(v, hs, ls);
    *reinterpret_cast<ushort4*>(&dh[idx4]) = hs;
    *reinterpret_cast<ushort4*>(&dl[idx4]) = ls;
}

// ---------------------------------------------------------------------------
// Kernel 2: scores (HMMA 3xBF16): per bh, 128x128 tile = Q[128,64] @ K[128,64]^T
// ---------------------------------------------------------------------------
#define LDSA 40   // 32-wide k-tile padded to 40 halfs per row

__global__ __launch_bounds__(256, 1)
void scores_mma_kernel()
{
    __shared__ __align__(16) __nv_bfloat16 sAh[128 * LDSA], sAl[128 * LDSA];
    __shared__ __align__(16) __nv_bfloat16 sBh[128 * LDSA], sBl[128 * LDSA];

    const int tid = threadIdx.x;
    const int lane = tid & 31, wid = tid >> 5;
    const int wm = wid >> 1, wn = wid & 1;     // 4x2 warps: 32x64 each
    const int bh = blockIdx.z;
    const size_t base = (size_t)bh * Tt * Dd;
    const int row0 = blockIdx.y * 128;
    const int col0 = blockIdx.x * 128;

    const uint32_t uAh = smem_u32(sAh), uAl = smem_u32(sAl);
    const uint32_t uBh = smem_u32(sBh), uBl = smem_u32(sBl);

    float acc[2][8][4];
#pragma unroll
    for (int i = 0; i < 2; i++)
#pragma unroll
        for (int j = 0; j < 8; j++)
#pragma unroll
            for (int k = 0; k < 4; k++) acc[i][j][k] = 0.0f;

    for (int k0 = 0; k0 < 64; k0 += 32) {
#pragma unroll
        for (int c = 0; c < 2; c++) {
            const int ch = tid + c * 256;      // 0..511
            const int row = ch >> 2, kc = ch & 3;
            const size_t ga = base + (size_t)(row0 + row) * 64 + k0 + kc * 8;
            const size_t gb = base + (size_t)(col0 + row) * 64 + k0 + kc * 8;
            const int so = row * LDSA + kc * 8;
            *reinterpret_cast<uint4*>(&sAh[so]) = *reinterpret_cast<const uint4*>(&g_qhi[ga]);
            *reinterpret_cast<uint4*>(&sAl[so]) = *reinterpret_cast<const uint4*>(&g_qlo[ga]);
            *reinterpret_cast<uint4*>(&sBh[so]) = *reinterpret_cast<const uint4*>(&g_khi[gb]);
            *reinterpret_cast<uint4*>(&sBl[so]) = *reinterpret_cast<const uint4*>(&g_klo[gb]);
        }
        __syncthreads();

#pragma unroll
        for (int ks = 0; ks < 32; ks += 16) {
            uint32_t ah[2][4], al[2][4], bh2[8][2], bl2[8][2];
#pragma unroll
            for (int mt = 0; mt < 2; mt++) {
                load_a_frag(ah[mt], uAh, wm * 32 + mt * 16, ks, lane, LDSA);
                load_a_frag(al[mt], uAl, wm * 32 + mt * 16, ks, lane, LDSA);
            }
#pragma unroll
            for (int p = 0; p < 4; p++) {
                load_b_frag2(bh2[2 * p], bh2[2 * p + 1], uBh, wn * 64 + p * 16, ks, lane, LDSA);
                load_b_frag2(bl2[2 * p], bl2[2 * p + 1], uBl, wn * 64 + p * 16, ks, lane, LDSA);
            }
#pragma unroll
            for (int mt = 0; mt < 2; mt++)
#pragma unroll
                for (int nt = 0; nt < 8; nt++) {
                    mma16816(acc[mt][nt], ah[mt], bh2[nt]);
                    mma16816(acc[mt][nt], ah[mt], bl2[nt]);
                    mma16816(acc[mt][nt], al[mt], bh2[nt]);
                }
        }
        __syncthreads();
    }

    float* C = g_attn + (size_t)bh * Tt * Ss;
#pragma unroll
    for (int mt = 0; mt < 2; mt++)
#pragma unroll
        for (int nt = 0; nt < 8; nt++) {
            const int n = col0 + wn * 64 + nt * 8 + 2 * (lane & 3);
#pragma unroll
            for (int half = 0; half < 2; half++) {
                const int m = row0 + wm * 32 + mt * 16 + (lane >> 2) + half * 8;
                *reinterpret_cast<float2*>(&C[(size_t)m * Ss + n]) =
                    make_float2(acc[mt][nt][2 * half] * 0.125f,
                                acc[mt][nt][2 * half + 1] * 0.125f);
            }
        }
}

// ---------------------------------------------------------------------------
// Kernel 3: softmax in place + head-mean (identical to R2-passing code)
// ---------------------------------------------------------------------------
__global__ __launch_bounds__(256)
void softmax_kernel(float* __restrict__ wout)
{
    const int bt = blockIdx.x;
    const int b = bt / Tt, t = bt % Tt;
    const int tid = threadIdx.x;

    __shared__ float red[256];

    float wsum[8];
#pragma unroll
    for (int i = 0; i < 8; i++) wsum[i] = 0.0f;

    for (int h = 0; h < Hh; h++) {
        float* arow = g_attn + (((size_t)b * Hh + h) * Tt + t) * Ss;
        float lv[8];
        float lmax = -1e30f;
#pragma unroll
        for (int i = 0; i < 8; i++) {
            lv[i] = arow[tid + i * 256];
            lmax = fmaxf(lmax, lv[i]);
        }
        red[tid] = lmax;
        __syncthreads();
        for (int s = 128; s > 0; s >>= 1) {
            if (tid < s) red[tid] = fmaxf(red[tid], red[tid + s]);
            __syncthreads();
        }
        const float m = red[0];
        __syncthreads();
        float lsum = 0.0f;
#pragma unroll
        for (int i = 0; i < 8; i++) {
            lv[i] = __expf(lv[i] - m);
            lsum += lv[i];
        }
        red[tid] = lsum;
        __syncthreads();
        for (int s = 128; s > 0; s >>= 1) {
            if (tid < s) red[tid] += red[tid + s];
            __syncthreads();
        }
        const float inv = 1.0f / red[0];
        __syncthreads();
#pragma unroll
        for (int i = 0; i < 8; i++) {
            const float p = lv[i] * inv;
            arow[tid + i * 256] = p;
            wsum[i] += p * (1.0f / Hh);
        }
    }
#pragma unroll
    for (int i = 0; i < 8; i++)
        wout[(size_t)bt * Ss + tid + i * 256] = wsum[i];
}

// ---------------------------------------------------------------------------
// Kernel 4: ctx (HMMA 3xBF16): per bh, [128,64] tile = P[128,2048] @ V[2048,64]
// P (f32, normalized) and V (f32) are split to bf16 hi/lo during smem staging.
// ---------------------------------------------------------------------------
#define LDSV 72

__global__ __launch_bounds__(256, 1)
void ctx_mma_kernel()
{
    __shared__ __align__(16) __nv_bfloat16 sPh[128 * LDSA], sPl[128 * LDSA];
    __shared__ __align__(16) __nv_bfloat16 sVh[32 * LDSV],  sVl[32 * LDSV];

    const int tid = threadIdx.x;
    const int lane = tid & 31, wid = tid >> 5;   // warp owns rows wid*16..+16
    const int bh = blockIdx.z;
    const int b = bh >> 4, h = bh & 15;
    const int row0 = blockIdx.y * 128;
    const size_t pbase = (size_t)bh * Tt * Ss;
    const size_t vbase = (size_t)bh * Ss * Dd;

    const uint32_t uPh = smem_u32(sPh), uPl = smem_u32(sPl);
    const uint32_t uVh = smem_u32(sVh), uVl = smem_u32(sVl);

    float acc[8][4];
#pragma unroll
    for (int j = 0; j < 8; j++)
#pragma unroll
        for (int k = 0; k < 4; k++) acc[j][k] = 0.0f;

    for (int k0 = 0; k0 < Ss; k0 += 32) {
        // P tile 128x32 f32 -> split bf16 (1024 float4 chunks, 4 per thread)
#pragma unroll
        for (int c = 0; c < 4; c++) {
            const int ch = tid + c * 256;          // 0..1023
            const int row = ch >> 3, kc = ch & 7;  // 8 chunks/row, 4 floats each
            float4 v = *reinterpret_cast<const float4*>(
                &g_attn[pbase + (size_t)(row0 + row) * Ss + k0 + kc * 4]);
            ushort4 hs, ls;
            split4(v, hs, ls);
            const int so = row * LDSA + kc * 4;
            *reinterpret_cast<ushort4*>(&sPh[so]) = hs;
            *reinterpret_cast<ushort4*>(&sPl[so]) = ls;
        }
        // V tile 32x64 f32 -> split bf16 (512 float4 chunks, 2 per thread)
#pragma unroll
        for (int c = 0; c < 2; c++) {
            const int ch = tid + c * 256;           // 0..511
            const int row = ch >> 4, dc = ch & 15;  // 16 chunks/row
            float4 v = *reinterpret_cast<const float4*>(
                &g_vp[vbase + (size_t)(k0 + row) * Dd + dc * 4]);
            ushort4 hs, ls;
            split4(v, hs, ls);
            const int so = row * LDSV + dc * 4;
            *reinterpret_cast<ushort4*>(&sVh[so]) = hs;
            *reinterpret_cast<ushort4*>(&sVl[so]) = ls;
        }
        __syncthreads();

#pragma unroll
        for (int ks = 0; ks < 32; ks += 16) {
            uint32_t ah[4], al[4], bh2[8][2], bl2[8][2];
            load_a_frag(ah, uPh, wid * 16, ks, lane, LDSA);
            load_a_frag(al, uPl, wid * 16, ks, lane, LDSA);
#pragma unroll
            for (int p = 0; p < 4; p++) {
                load_b_frag2_trans(bh2[2 * p], bh2[2 * p + 1], uVh, p * 16, ks, lane, LDSV);
                load_b_frag2_trans(bl2[2 * p], bl2[2 * p + 1], uVl, p * 16, ks, lane, LDSV);
            }
#pragma unroll
            for (int nt = 0; nt < 8; nt++) {
                mma16816(acc[nt], ah, bh2[nt]);
                mma16816(acc[nt], ah, bl2[nt]);
                mma16816(acc[nt], al, bh2[nt]);
            }
        }
        __syncthreads();
    }

    // epilogue: f32 ctx at (b, t, h*64 + d)
#pragma unroll
    for (int nt = 0; nt < 8; nt++) {
        const int d = nt * 8 + 2 * (lane & 3);
#pragma unroll
        for (int half = 0; half < 2; half++) {
            const int t = row0 + wid * 16 + (lane >> 2) + half * 8;
            *reinterpret_cast<float2*>(
                &g_ctx[((size_t)b * Tt + t) * Ee + h * Dd + d]) =
                make_float2(acc[nt][2 * half], acc[nt][2 * half + 1]);
        }
    }
}

// ---------------------------------------------------------------------------
// Kernel 5: out projection (fp32 FFMA — identical to R2-passing code)
// ---------------------------------------------------------------------------
__global__ __launch_bounds__(256)
void outproj_kernel(const float* __restrict__ w,
                    const float* __restrict__ bias,
                    float* __restrict__ out)
{
    __shared__ float As[16][65];
    __shared__ float Bs[16][65];

    const int tx = threadIdx.x, ty = threadIdx.y;
    const int tid = ty * 16 + tx;
    const int row0 = blockIdx.y * 64;
    const int col0 = blockIdx.x * 64;
    const int lr = tid >> 2;
    const int lc = (tid & 3) * 4;

    float acc[4][4];
#pragma unroll
    for (int i = 0; i < 4; i++)
#pragma unroll
        for (int j = 0; j < 4; j++) acc[i][j] = 0.0f;

    for (int k0 = 0; k0 < Ee; k0 += 16) {
        float4 av = *reinterpret_cast<const float4*>(
            &g_ctx[(size_t)(row0 + lr) * Ee + k0 + lc]);
        As[lc + 0][lr] = av.x; As[lc + 1][lr] = av.y;
        As[lc + 2][lr] = av.z; As[lc + 3][lr] = av.w;
        float4 bv = *reinterpret_cast<const float4*>(
            &w[(size_t)(col0 + lr) * Ee + k0 + lc]);
        Bs[lc + 0][lr] = bv.x; Bs[lc + 1][lr] = bv.y;
        Bs[lc + 2][lr] = bv.z; Bs[lc + 3][lr] = bv.w;
        __syncthreads();
#pragma unroll
        for (int kk = 0; kk < 16; kk++) {
            float a[4], bvv[4];
#pragma unroll
            for (int i = 0; i < 4; i++) a[i] = As[kk][ty * 4 + i];
#pragma unroll
            for (int j = 0; j < 4; j++) bvv[j] = Bs[kk][tx * 4 + j];
#pragma unroll
            for (int i = 0; i < 4; i++)
#pragma unroll
                for (int j = 0; j < 4; j++)
                    acc[i][j] = fmaf(a[i], bvv[j], acc[i][j]);
        }
        __syncthreads();
    }

#pragma unroll
    for (int i = 0; i < 4; i++) {
        const int m = row0 + ty * 4 + i;
#pragma unroll
        for (int j = 0; j < 4; j++) {
            const int n = col0 + tx * 4 + j;
            out[(size_t)m * Ee + n] = acc[i][j] + bias[n];
        }
    }
}

// ---------------------------------------------------------------------------
extern "C" void kernel_launch(void* const* d_in, const int* in_sizes, int n_in,
                              void* d_out, int out_size)
{
    const float* q    = (const float*)d_in[0];
    const float* kv   = (const float*)d_in[1];
    const float* ipw  = (const float*)d_in[2];
    const float* ipb  = (const float*)d_in[3];
    const float* opw  = (const float*)d_in[4];
    const float* opb  = (const float*)d_in[5];
    float* out = (float*)d_out;                       // (B,T,H,D) flattened
    float* wout = out + (size_t)Bb * Tt * Ee;         // (B,T,S) flattened

    dim3 thr(16, 16);

    // 1. QKV projections (fp32, known-good)
    proj_kernel<<<dim3(Ee / 64, (Bb * Tt) / 64, 3), thr>>>(q, kv, ipw, ipb);

    // 1b. split q/k -> bf16 hi/lo
    convert_qk_kernel<<<dim3(4096, 1, 2), 256>>>();

    // 2. scores (HMMA 3xBF16)
    scores_mma_kernel<<<dim3(16, 16, Bb * Hh), 256>>>();

    // 3. softmax + head-mean weights (known-good)
    softmax_kernel<<<Bb * Tt, 256>>>(wout);

    // 4. ctx = P @ V (HMMA 3xBF16, in-staging split)
    ctx_mma_kernel<<<dim3(1, 16, Bb * Hh), 256>>>();

    // 5. out projection (fp32, known-good)
    outproj_kernel<<<dim3(Ee / 64, (Bb * Tt) / 64), thr>>>(opw, opb, out);
}

// round 12
// speedup vs baseline: 2.3237x; 1.6393x over previous
#include <cuda_runtime.h>
#include <cuda_bf16.h>
#include <cstdint>
#include <math.h>

#define Bb 2
#define Tt 2048
#define Ss 2048
#define Hh 16
#define Dd 64
#define Ee 1024

// ---------------------------------------------------------------------------
// Scratch (static __device__ — allocation-free per harness rules).
// NOTE: these are referenced ONLY from device code. Passing them as kernel
// arguments from host code yields garbage addresses (R7/R11 root cause).
// ---------------------------------------------------------------------------
__device__ float g_qp[(size_t)Bb * Hh * Tt * Dd];   // (B,H,T,D)
__device__ float g_kp[(size_t)Bb * Hh * Ss * Dd];   // (B,H,S,D)
__device__ float g_vp[(size_t)Bb * Hh * Ss * Dd];   // (B,H,S,D)
__device__ float g_attn[(size_t)Bb * Hh * Tt * Ss]; // (B,H,T,S)  512 MB
__device__ float g_ctx[(size_t)Bb * Tt * Ee];       // (B,T,E)

#define PROJ_ELEMS ((size_t)Bb * Hh * Tt * Dd)
__device__ __nv_bfloat16 g_qhi[PROJ_ELEMS], g_qlo[PROJ_ELEMS];
__device__ __nv_bfloat16 g_khi[PROJ_ELEMS], g_klo[PROJ_ELEMS];

// ---------------------------------------------------------------------------
// Warp MMA primitives (validated in R9)
// ---------------------------------------------------------------------------
__device__ __forceinline__ uint32_t smem_u32(const void* p) {
    uint32_t a;
    asm("{ .reg .u64 t; cvta.to.shared.u64 t, %1; cvt.u32.u64 %0, t; }"
        : "=r"(a) : "l"(p));
    return a;
}

__device__ __forceinline__ void mma16816(float* d, const uint32_t* a, const uint32_t* b) {
    asm volatile(
        "mma.sync.aligned.m16n8k16.row.col.f32.bf16.bf16.f32 "
        "{%0,%1,%2,%3}, {%4,%5,%6,%7}, {%8,%9}, {%0,%1,%2,%3};"
        : "+f"(d[0]), "+f"(d[1]), "+f"(d[2]), "+f"(d[3])
        : "r"(a[0]), "r"(a[1]), "r"(a[2]), "r"(a[3]), "r"(b[0]), "r"(b[1]));
}

#define LDSM4(R0,R1,R2,R3,ADDR) \
    asm volatile("ldmatrix.sync.aligned.m8n8.x4.shared.b16 {%0,%1,%2,%3}, [%4];" \
        : "=r"(R0),"=r"(R1),"=r"(R2),"=r"(R3) : "r"(ADDR))
#define LDSM4T(R0,R1,R2,R3,ADDR) \
    asm volatile("ldmatrix.sync.aligned.m8n8.x4.trans.shared.b16 {%0,%1,%2,%3}, [%4];" \
        : "=r"(R0),"=r"(R1),"=r"(R2),"=r"(R3) : "r"(ADDR))

__device__ __forceinline__ void load_a_frag(uint32_t* fr, uint32_t base_u32,
                                            int mbase, int ks, int lane, int lds) {
    const int row = mbase + (lane & 15);
    const int col = ks + ((lane >> 4) << 3);
    LDSM4(fr[0], fr[1], fr[2], fr[3], base_u32 + (uint32_t)(row * lds + col) * 2u);
}
__device__ __forceinline__ void load_b_frag2(uint32_t* f0, uint32_t* f1, uint32_t base_u32,
                                             int nb, int ks, int lane, int lds) {
    const int g = lane >> 3, r = lane & 7;
    const int row = nb + ((g >> 1) << 3) + r;
    const int col = ks + ((g & 1) << 3);
    LDSM4(f0[0], f0[1], f1[0], f1[1], base_u32 + (uint32_t)(row * lds + col) * 2u);
}
__device__ __forceinline__ void load_b_frag2_trans(uint32_t* f0, uint32_t* f1, uint32_t base_u32,
                                                   int db, int ks, int lane, int lds) {
    const int g = lane >> 3, r = lane & 7;
    const int row = ks + ((g & 1) << 3) + r;
    const int col = db + ((g >> 1) << 3);
    LDSM4T(f0[0], f0[1], f1[0], f1[1], base_u32 + (uint32_t)(row * lds + col) * 2u);
}

__device__ __forceinline__ void split4(float4 v, ushort4& hs, ushort4& ls)
{
    __nv_bfloat16 h0 = __float2bfloat16(v.x);
    __nv_bfloat16 h1 = __float2bfloat16(v.y);
    __nv_bfloat16 h2 = __float2bfloat16(v.z);
    __nv_bfloat16 h3 = __float2bfloat16(v.w);
    __nv_bfloat16 l0 = __float2bfloat16(v.x - __bfloat162float(h0));
    __nv_bfloat16 l1 = __float2bfloat16(v.y - __bfloat162float(h1));
    __nv_bfloat16 l2 = __float2bfloat16(v.z - __bfloat162float(h2));
    __nv_bfloat16 l3 = __float2bfloat16(v.w - __bfloat162float(h3));
    hs = make_ushort4(__bfloat16_as_ushort(h0), __bfloat16_as_ushort(h1),
                      __bfloat16_as_ushort(h2), __bfloat16_as_ushort(h3));
    ls = make_ushort4(__bfloat16_as_ushort(l0), __bfloat16_as_ushort(l1),
                      __bfloat16_as_ushort(l2), __bfloat16_as_ushort(l3));
}

#define LDSA 40   // 32-wide k-tile padded to 40 halfs per row

// ---------------------------------------------------------------------------
// Kernel 1/5: projection GEMM (HMMA 3xBF16), in-staging split of f32 inputs.
// C[128x128 tile] = A[M,K=1024] @ W[N=1024,K=1024]^T + bias
// mode 0/1/2 (outmode=0, grid.z selects): A = q / kv(k) / kv(v) from harness
//            pointers; scatter f32 into g_qp/g_kp/g_vp (device globals,
//            resolved in device code).
// mode 3 (outmode=3): A = g_ctx (resolved IN DEVICE CODE — the R11 fix);
//            plain f32 row-major into outPlain (harness d_out).
// ---------------------------------------------------------------------------
__global__ __launch_bounds__(256, 1)
void proj_mma_kernel(const float* __restrict__ qA,
                     const float* __restrict__ kvA,
                     const float* __restrict__ Wbase,
                     const float* __restrict__ biasBase,
                     float* __restrict__ outPlain,
                     int outmode)
{
    __shared__ __align__(16) __nv_bfloat16 sAh[128 * LDSA], sAl[128 * LDSA];
    __shared__ __align__(16) __nv_bfloat16 sBh[128 * LDSA], sBl[128 * LDSA];

    const int tid = threadIdx.x;
    const int lane = tid & 31, wid = tid >> 5;
    const int wm = wid >> 1, wn = wid & 1;     // 4x2 warps: 32x64 each
    const int z = (outmode == 3) ? 0 : blockIdx.z;
    const int mode = (outmode == 3) ? 3 : z;

    const float* A;
    int lda;
    if (mode == 3)      { A = g_ctx;       lda = Ee; }      // device-code symbol
    else if (z == 0)    { A = qA;          lda = Ee; }
    else if (z == 1)    { A = kvA;         lda = 2 * Ee; }
    else                { A = kvA + Ee;    lda = 2 * Ee; }
    const float* W    = Wbase + (size_t)z * Ee * Ee;
    const float* bias = biasBase + z * Ee;

    const int row0 = blockIdx.y * 128;
    const int col0 = blockIdx.x * 128;

    const uint32_t uAh = smem_u32(sAh), uAl = smem_u32(sAl);
    const uint32_t uBh = smem_u32(sBh), uBl = smem_u32(sBl);

    float acc[2][8][4];
#pragma unroll
    for (int i = 0; i < 2; i++)
#pragma unroll
        for (int j = 0; j < 8; j++)
#pragma unroll
            for (int k = 0; k < 4; k++) acc[i][j][k] = 0.0f;

    for (int k0 = 0; k0 < Ee; k0 += 32) {
        // stage A tile 128x32 f32 -> split bf16 (1024 float4 chunks, 4/thread)
#pragma unroll
        for (int c = 0; c < 4; c++) {
            const int ch = tid + c * 256;          // 0..1023
            const int row = ch >> 3, kc = ch & 7;  // 8 chunks/row
            float4 v = *reinterpret_cast<const float4*>(
                &A[(size_t)(row0 + row) * lda + k0 + kc * 4]);
            ushort4 hs, ls;
            split4(v, hs, ls);
            const int so = row * LDSA + kc * 4;
            *reinterpret_cast<ushort4*>(&sAh[so]) = hs;
            *reinterpret_cast<ushort4*>(&sAl[so]) = ls;
        }
        // stage W tile 128x32 f32 -> split bf16
#pragma unroll
        for (int c = 0; c < 4; c++) {
            const int ch = tid + c * 256;
            const int row = ch >> 3, kc = ch & 7;
            float4 v = *reinterpret_cast<const float4*>(
                &W[(size_t)(col0 + row) * Ee + k0 + kc * 4]);
            ushort4 hs, ls;
            split4(v, hs, ls);
            const int so = row * LDSA + kc * 4;
            *reinterpret_cast<ushort4*>(&sBh[so]) = hs;
            *reinterpret_cast<ushort4*>(&sBl[so]) = ls;
        }
        __syncthreads();

#pragma unroll
        for (int ks = 0; ks < 32; ks += 16) {
            uint32_t ah[2][4], al[2][4], bh2[8][2], bl2[8][2];
#pragma unroll
            for (int mt = 0; mt < 2; mt++) {
                load_a_frag(ah[mt], uAh, wm * 32 + mt * 16, ks, lane, LDSA);
                load_a_frag(al[mt], uAl, wm * 32 + mt * 16, ks, lane, LDSA);
            }
#pragma unroll
            for (int p = 0; p < 4; p++) {
                load_b_frag2(bh2[2 * p], bh2[2 * p + 1], uBh, wn * 64 + p * 16, ks, lane, LDSA);
                load_b_frag2(bl2[2 * p], bl2[2 * p + 1], uBl, wn * 64 + p * 16, ks, lane, LDSA);
            }
#pragma unroll
            for (int mt = 0; mt < 2; mt++)
#pragma unroll
                for (int nt = 0; nt < 8; nt++) {
                    mma16816(acc[mt][nt], ah[mt], bh2[nt]);
                    mma16816(acc[mt][nt], ah[mt], bl2[nt]);
                    mma16816(acc[mt][nt], al[mt], bh2[nt]);
                }
        }
        __syncthreads();
    }

    // epilogue: f32 + bias; scatter (modes 0-2) or plain (mode 3)
    float* scatTgt = (mode == 0) ? g_qp : (mode == 1) ? g_kp : g_vp;
#pragma unroll
    for (int mt = 0; mt < 2; mt++) {
#pragma unroll
        for (int nt = 0; nt < 8; nt++) {
            const int n = col0 + wn * 64 + nt * 8 + 2 * (lane & 3);
            const float b0 = bias[n], b1 = bias[n + 1];
#pragma unroll
            for (int half = 0; half < 2; half++) {
                const int m = row0 + wm * 32 + mt * 16 + (lane >> 2) + half * 8;
                const float v0 = acc[mt][nt][2 * half + 0] + b0;
                const float v1 = acc[mt][nt][2 * half + 1] + b1;
                if (mode == 3) {
                    *reinterpret_cast<float2*>(&outPlain[(size_t)m * Ee + n]) =
                        make_float2(v0, v1);
                } else {
                    const int bidx = m >> 11, t = m & 2047;
                    const int h = n >> 6, d = n & 63;
                    *reinterpret_cast<float2*>(
                        &scatTgt[(((size_t)bidx * Hh + h) * Tt + t) * Dd + d]) =
                        make_float2(v0, v1);
                }
            }
        }
    }
}

// ---------------------------------------------------------------------------
// Kernel 1b: split q/k fp32 -> bf16 hi/lo (unchanged, validated)
// ---------------------------------------------------------------------------
__global__ __launch_bounds__(256)
void convert_qk_kernel()
{
    const int z = blockIdx.z;
    const size_t idx4 = ((size_t)blockIdx.x * 256 + threadIdx.x) * 4;
    const float* src = (z == 0) ? g_qp : g_kp;
    __nv_bfloat16* dh = (z == 0) ? g_qhi : g_khi;
    __nv_bfloat16* dl = (z == 0) ? g_qlo : g_klo;
    float4 v = *reinterpret_cast<const float4*>(&src[idx4]);
    ushort4 hs, ls;
    split4(v, hs, ls);
    *reinterpret_cast<ushort4*>(&dh[idx4]) = hs;
    *reinterpret_cast<ushort4*>(&dl[idx4]) = ls;
}

// ---------------------------------------------------------------------------
// Kernel 2: scores (HMMA 3xBF16) — unchanged, validated
// ---------------------------------------------------------------------------
__global__ __launch_bounds__(256, 1)
void scores_mma_kernel()
{
    __shared__ __align__(16) __nv_bfloat16 sAh[128 * LDSA], sAl[128 * LDSA];
    __shared__ __align__(16) __nv_bfloat16 sBh[128 * LDSA], sBl[128 * LDSA];

    const int tid = threadIdx.x;
    const int lane = tid & 31, wid = tid >> 5;
    const int wm = wid >> 1, wn = wid & 1;
    const int bh = blockIdx.z;
    const size_t base = (size_t)bh * Tt * Dd;
    const int row0 = blockIdx.y * 128;
    const int col0 = blockIdx.x * 128;

    const uint32_t uAh = smem_u32(sAh), uAl = smem_u32(sAl);
    const uint32_t uBh = smem_u32(sBh), uBl = smem_u32(sBl);

    float acc[2][8][4];
#pragma unroll
    for (int i = 0; i < 2; i++)
#pragma unroll
        for (int j = 0; j < 8; j++)
#pragma unroll
            for (int k = 0; k < 4; k++) acc[i][j][k] = 0.0f;

    for (int k0 = 0; k0 < 64; k0 += 32) {
#pragma unroll
        for (int c = 0; c < 2; c++) {
            const int ch = tid + c * 256;
            const int row = ch >> 2, kc = ch & 3;
            const size_t ga = base + (size_t)(row0 + row) * 64 + k0 + kc * 8;
            const size_t gb = base + (size_t)(col0 + row) * 64 + k0 + kc * 8;
            const int so = row * LDSA + kc * 8;
            *reinterpret_cast<uint4*>(&sAh[so]) = *reinterpret_cast<const uint4*>(&g_qhi[ga]);
            *reinterpret_cast<uint4*>(&sAl[so]) = *reinterpret_cast<const uint4*>(&g_qlo[ga]);
            *reinterpret_cast<uint4*>(&sBh[so]) = *reinterpret_cast<const uint4*>(&g_khi[gb]);
            *reinterpret_cast<uint4*>(&sBl[so]) = *reinterpret_cast<const uint4*>(&g_klo[gb]);
        }
        __syncthreads();

#pragma unroll
        for (int ks = 0; ks < 32; ks += 16) {
            uint32_t ah[2][4], al[2][4], bh2[8][2], bl2[8][2];
#pragma unroll
            for (int mt = 0; mt < 2; mt++) {
                load_a_frag(ah[mt], uAh, wm * 32 + mt * 16, ks, lane, LDSA);
                load_a_frag(al[mt], uAl, wm * 32 + mt * 16, ks, lane, LDSA);
            }
#pragma unroll
            for (int p = 0; p < 4; p++) {
                load_b_frag2(bh2[2 * p], bh2[2 * p + 1], uBh, wn * 64 + p * 16, ks, lane, LDSA);
                load_b_frag2(bl2[2 * p], bl2[2 * p + 1], uBl, wn * 64 + p * 16, ks, lane, LDSA);
            }
#pragma unroll
            for (int mt = 0; mt < 2; mt++)
#pragma unroll
                for (int nt = 0; nt < 8; nt++) {
                    mma16816(acc[mt][nt], ah[mt], bh2[nt]);
                    mma16816(acc[mt][nt], ah[mt], bl2[nt]);
                    mma16816(acc[mt][nt], al[mt], bh2[nt]);
                }
        }
        __syncthreads();
    }

    float* C = g_attn + (size_t)bh * Tt * Ss;
#pragma unroll
    for (int mt = 0; mt < 2; mt++)
#pragma unroll
        for (int nt = 0; nt < 8; nt++) {
            const int n = col0 + wn * 64 + nt * 8 + 2 * (lane & 3);
#pragma unroll
            for (int half = 0; half < 2; half++) {
                const int m = row0 + wm * 32 + mt * 16 + (lane >> 2) + half * 8;
                *reinterpret_cast<float2*>(&C[(size_t)m * Ss + n]) =
                    make_float2(acc[mt][nt][2 * half] * 0.125f,
                                acc[mt][nt][2 * half + 1] * 0.125f);
            }
        }
}

// ---------------------------------------------------------------------------
// Kernel 3: softmax in place + head-mean (unchanged, validated)
// ---------------------------------------------------------------------------
__global__ __launch_bounds__(256)
void softmax_kernel(float* __restrict__ wout)
{
    const int bt = blockIdx.x;
    const int b = bt / Tt, t = bt % Tt;
    const int tid = threadIdx.x;

    __shared__ float red[256];

    float wsum[8];
#pragma unroll
    for (int i = 0; i < 8; i++) wsum[i] = 0.0f;

    for (int h = 0; h < Hh; h++) {
        float* arow = g_attn + (((size_t)b * Hh + h) * Tt + t) * Ss;
        float lv[8];
        float lmax = -1e30f;
#pragma unroll
        for (int i = 0; i < 8; i++) {
            lv[i] = arow[tid + i * 256];
            lmax = fmaxf(lmax, lv[i]);
        }
        red[tid] = lmax;
        __syncthreads();
        for (int s = 128; s > 0; s >>= 1) {
            if (tid < s) red[tid] = fmaxf(red[tid], red[tid + s]);
            __syncthreads();
        }
        const float m = red[0];
        __syncthreads();
        float lsum = 0.0f;
#pragma unroll
        for (int i = 0; i < 8; i++) {
            lv[i] = __expf(lv[i] - m);
            lsum += lv[i];
        }
        red[tid] = lsum;
        __syncthreads();
        for (int s = 128; s > 0; s >>= 1) {
            if (tid < s) red[tid] += red[tid + s];
            __syncthreads();
        }
        const float inv = 1.0f / red[0];
        __syncthreads();
#pragma unroll
        for (int i = 0; i < 8; i++) {
            const float p = lv[i] * inv;
            arow[tid + i * 256] = p;
            wsum[i] += p * (1.0f / Hh);
        }
    }
#pragma unroll
    for (int i = 0; i < 8; i++)
        wout[(size_t)bt * Ss + tid + i * 256] = wsum[i];
}

// ---------------------------------------------------------------------------
// Kernel 4: ctx (HMMA 3xBF16, in-staging split) — unchanged, validated
// ---------------------------------------------------------------------------
#define LDSV 72

__global__ __launch_bounds__(256, 1)
void ctx_mma_kernel()
{
    __shared__ __align__(16) __nv_bfloat16 sPh[128 * LDSA], sPl[128 * LDSA];
    __shared__ __align__(16) __nv_bfloat16 sVh[32 * LDSV],  sVl[32 * LDSV];

    const int tid = threadIdx.x;
    const int lane = tid & 31, wid = tid >> 5;
    const int bh = blockIdx.z;
    const int b = bh >> 4, h = bh & 15;
    const int row0 = blockIdx.y * 128;
    const size_t pbase = (size_t)bh * Tt * Ss;
    const size_t vbase = (size_t)bh * Ss * Dd;

    const uint32_t uPh = smem_u32(sPh), uPl = smem_u32(sPl);
    const uint32_t uVh = smem_u32(sVh), uVl = smem_u32(sVl);

    float acc[8][4];
#pragma unroll
    for (int j = 0; j < 8; j++)
#pragma unroll
        for (int k = 0; k < 4; k++) acc[j][k] = 0.0f;

    for (int k0 = 0; k0 < Ss; k0 += 32) {
#pragma unroll
        for (int c = 0; c < 4; c++) {
            const int ch = tid + c * 256;
            const int row = ch >> 3, kc = ch & 7;
            float4 v = *reinterpret_cast<const float4*>(
                &g_attn[pbase + (size_t)(row0 + row) * Ss + k0 + kc * 4]);
            ushort4 hs, ls;
            split4(v, hs, ls);
            const int so = row * LDSA + kc * 4;
            *reinterpret_cast<ushort4*>(&sPh[so]) = hs;
            *reinterpret_cast<ushort4*>(&sPl[so]) = ls;
        }
#pragma unroll
        for (int c = 0; c < 2; c++) {
            const int ch = tid + c * 256;
            const int row = ch >> 4, dc = ch & 15;
            float4 v = *reinterpret_cast<const float4*>(
                &g_vp[vbase + (size_t)(k0 + row) * Dd + dc * 4]);
            ushort4 hs, ls;
            split4(v, hs, ls);
            const int so = row * LDSV + dc * 4;
            *reinterpret_cast<ushort4*>(&sVh[so]) = hs;
            *reinterpret_cast<ushort4*>(&sVl[so]) = ls;
        }
        __syncthreads();

#pragma unroll
        for (int ks = 0; ks < 32; ks += 16) {
            uint32_t ah[4], al[4], bh2[8][2], bl2[8][2];
            load_a_frag(ah, uPh, wid * 16, ks, lane, LDSA);
            load_a_frag(al, uPl, wid * 16, ks, lane, LDSA);
#pragma unroll
            for (int p = 0; p < 4; p++) {
                load_b_frag2_trans(bh2[2 * p], bh2[2 * p + 1], uVh, p * 16, ks, lane, LDSV);
                load_b_frag2_trans(bl2[2 * p], bl2[2 * p + 1], uVl, p * 16, ks, lane, LDSV);
            }
#pragma unroll
            for (int nt = 0; nt < 8; nt++) {
                mma16816(acc[nt], ah, bh2[nt]);
                mma16816(acc[nt], ah, bl2[nt]);
                mma16816(acc[nt], al, bh2[nt]);
            }
        }
        __syncthreads();
    }

#pragma unroll
    for (int nt = 0; nt < 8; nt++) {
        const int d = nt * 8 + 2 * (lane & 3);
#pragma unroll
        for (int half = 0; half < 2; half++) {
            const int t = row0 + wid * 16 + (lane >> 2) + half * 8;
            *reinterpret_cast<float2*>(
                &g_ctx[((size_t)b * Tt + t) * Ee + h * Dd + d]) =
                make_float2(acc[nt][2 * half], acc[nt][2 * half + 1]);
        }
    }
}

// ---------------------------------------------------------------------------
extern "C" void kernel_launch(void* const* d_in, const int* in_sizes, int n_in,
                              void* d_out, int out_size)
{
    const float* q    = (const float*)d_in[0];
    const float* kv   = (const float*)d_in[1];
    const float* ipw  = (const float*)d_in[2];
    const float* ipb  = (const float*)d_in[3];
    const float* opw  = (const float*)d_in[4];
    const float* opb  = (const float*)d_in[5];
    float* out = (float*)d_out;                       // (B,T,H,D) flattened
    float* wout = out + (size_t)Bb * Tt * Ee;         // (B,T,S) flattened

    // 1. QKV projections (HMMA 3xBF16) -> f32 g_qp/g_kp/g_vp
    proj_mma_kernel<<<dim3(8, 32, 3), 256>>>(q, kv, ipw, ipb, nullptr, 0);

    // 1b. split q/k -> bf16 hi/lo
    convert_qk_kernel<<<dim3(4096, 1, 2), 256>>>();

    // 2. scores (HMMA 3xBF16)
    scores_mma_kernel<<<dim3(16, 16, Bb * Hh), 256>>>();

    // 3. softmax + head-mean weights
    softmax_kernel<<<Bb * Tt, 256>>>(wout);

    // 4. ctx = P @ V (HMMA 3xBF16, in-staging split)
    ctx_mma_kernel<<<dim3(1, 16, Bb * Hh), 256>>>();

    // 5. out projection (HMMA 3xBF16): A = g_ctx selected in device code
    proj_mma_kernel<<<dim3(8, 32, 1), 256>>>(nullptr, nullptr, opw, opb, out, 3);
}

// round 13
// speedup vs baseline: 2.5386x; 1.0925x over previous
#include <cuda_runtime.h>
#include <cuda_bf16.h>
#include <cstdint>
#include <math.h>

#define Bb 2
#define Tt 2048
#define Ss 2048
#define Hh 16
#define Dd 64
#define Ee 1024

// ---------------------------------------------------------------------------
// Scratch (static __device__). Referenced ONLY from device code — never passed
// as kernel arguments from host (R7/R11 root cause).
// ---------------------------------------------------------------------------
__device__ float g_attn[(size_t)Bb * Hh * Tt * Ss];        // f32 scores (512 MB)

__device__ __nv_bfloat16 g_ahi[(size_t)3 * 4096 * 1024];   // qkv activations split
__device__ __nv_bfloat16 g_alo[(size_t)3 * 4096 * 1024];
__device__ __nv_bfloat16 g_whi[(size_t)4 * 1024 * 1024];   // in_proj(3)+out_proj(1)
__device__ __nv_bfloat16 g_wlo[(size_t)4 * 1024 * 1024];

#define PROJ_ELEMS ((size_t)Bb * Hh * Tt * Dd)
__device__ __nv_bfloat16 g_qhi[PROJ_ELEMS], g_qlo[PROJ_ELEMS];
__device__ __nv_bfloat16 g_khi[PROJ_ELEMS], g_klo[PROJ_ELEMS];
__device__ __nv_bfloat16 g_vhi[PROJ_ELEMS], g_vlo[PROJ_ELEMS];

__device__ __nv_bfloat16 g_phi[(size_t)Bb * Hh * Tt * Ss]; // softmax probs split
__device__ __nv_bfloat16 g_plo[(size_t)Bb * Hh * Tt * Ss];

__device__ __nv_bfloat16 g_chi[(size_t)4096 * 1024];       // ctx split
__device__ __nv_bfloat16 g_clo[(size_t)4096 * 1024];

// ---------------------------------------------------------------------------
// Primitives
// ---------------------------------------------------------------------------
__device__ __forceinline__ uint32_t smem_u32(const void* p) {
    uint32_t a;
    asm("{ .reg .u64 t; cvta.to.shared.u64 t, %1; cvt.u32.u64 %0, t; }"
        : "=r"(a) : "l"(p));
    return a;
}

__device__ __forceinline__ void mma16816(float* d, const uint32_t* a, const uint32_t* b) {
    asm volatile(
        "mma.sync.aligned.m16n8k16.row.col.f32.bf16.bf16.f32 "
        "{%0,%1,%2,%3}, {%4,%5,%6,%7}, {%8,%9}, {%0,%1,%2,%3};"
        : "+f"(d[0]), "+f"(d[1]), "+f"(d[2]), "+f"(d[3])
        : "r"(a[0]), "r"(a[1]), "r"(a[2]), "r"(a[3]), "r"(b[0]), "r"(b[1]));
}

#define LDSM4(R0,R1,R2,R3,ADDR) \
    asm volatile("ldmatrix.sync.aligned.m8n8.x4.shared.b16 {%0,%1,%2,%3}, [%4];" \
        : "=r"(R0),"=r"(R1),"=r"(R2),"=r"(R3) : "r"(ADDR))
#define LDSM4T(R0,R1,R2,R3,ADDR) \
    asm volatile("ldmatrix.sync.aligned.m8n8.x4.trans.shared.b16 {%0,%1,%2,%3}, [%4];" \
        : "=r"(R0),"=r"(R1),"=r"(R2),"=r"(R3) : "r"(ADDR))

__device__ __forceinline__ void load_a_frag(uint32_t* fr, uint32_t base_u32,
                                            int mbase, int ks, int lane, int lds) {
    const int row = mbase + (lane & 15);
    const int col = ks + ((lane >> 4) << 3);
    LDSM4(fr[0], fr[1], fr[2], fr[3], base_u32 + (uint32_t)(row * lds + col) * 2u);
}
__device__ __forceinline__ void load_b_frag2(uint32_t* f0, uint32_t* f1, uint32_t base_u32,
                                             int nb, int ks, int lane, int lds) {
    const int g = lane >> 3, r = lane & 7;
    const int row = nb + ((g >> 1) << 3) + r;
    const int col = ks + ((g & 1) << 3);
    LDSM4(f0[0], f0[1], f1[0], f1[1], base_u32 + (uint32_t)(row * lds + col) * 2u);
}
__device__ __forceinline__ void load_b_frag2_trans(uint32_t* f0, uint32_t* f1, uint32_t base_u32,
                                                   int db, int ks, int lane, int lds) {
    const int g = lane >> 3, r = lane & 7;
    const int row = ks + ((g & 1) << 3) + r;
    const int col = db + ((g >> 1) << 3);
    LDSM4T(f0[0], f0[1], f1[0], f1[1], base_u32 + (uint32_t)(row * lds + col) * 2u);
}

__device__ __forceinline__ void cp16(uint32_t saddr, const void* gptr) {
    asm volatile("cp.async.cg.shared.global [%0], [%1], 16;"
                 :: "r"(saddr), "l"(gptr));
}
#define CP_COMMIT() asm volatile("cp.async.commit_group;" ::: "memory")
#define CP_WAIT1()  asm volatile("cp.async.wait_group 1;" ::: "memory")
#define CP_WAIT0()  asm volatile("cp.async.wait_group 0;" ::: "memory")

__device__ __forceinline__ void split4(float4 v, ushort4& hs, ushort4& ls)
{
    __nv_bfloat16 h0 = __float2bfloat16(v.x);
    __nv_bfloat16 h1 = __float2bfloat16(v.y);
    __nv_bfloat16 h2 = __float2bfloat16(v.z);
    __nv_bfloat16 h3 = __float2bfloat16(v.w);
    __nv_bfloat16 l0 = __float2bfloat16(v.x - __bfloat162float(h0));
    __nv_bfloat16 l1 = __float2bfloat16(v.y - __bfloat162float(h1));
    __nv_bfloat16 l2 = __float2bfloat16(v.z - __bfloat162float(h2));
    __nv_bfloat16 l3 = __float2bfloat16(v.w - __bfloat162float(h3));
    hs = make_ushort4(__bfloat16_as_ushort(h0), __bfloat16_as_ushort(h1),
                      __bfloat16_as_ushort(h2), __bfloat16_as_ushort(h3));
    ls = make_ushort4(__bfloat16_as_ushort(l0), __bfloat16_as_ushort(l1),
                      __bfloat16_as_ushort(l2), __bfloat16_as_ushort(l3));
}
__device__ __forceinline__ void split2(float a, float b, uint32_t& hi, uint32_t& lo) {
    __nv_bfloat16 ha = __float2bfloat16(a), hb = __float2bfloat16(b);
    hi = ((uint32_t)__bfloat16_as_ushort(hb) << 16) | __bfloat16_as_ushort(ha);
    __nv_bfloat16 la = __float2bfloat16(a - __bfloat162float(ha));
    __nv_bfloat16 lb = __float2bfloat16(b - __bfloat162float(hb));
    lo = ((uint32_t)__bfloat16_as_ushort(lb) << 16) | __bfloat16_as_ushort(la);
}

// ---------------------------------------------------------------------------
// Conversion kernels (R7 logic, device-global outputs via symbols)
// ---------------------------------------------------------------------------
__global__ __launch_bounds__(256)
void convert_qkv_kernel(const float* __restrict__ q, const float* __restrict__ kv)
{
    const int z = blockIdx.z;
    const size_t idx4 = ((size_t)blockIdx.x * 256 + threadIdx.x) * 4;
    const size_t m = idx4 >> 10;
    const size_t e = idx4 & 1023;
    const float* src;
    if (z == 0)      src = q  + m * 1024 + e;
    else if (z == 1) src = kv + m * 2048 + e;
    else             src = kv + m * 2048 + 1024 + e;
    float4 v = *reinterpret_cast<const float4*>(src);
    ushort4 hs, ls;
    split4(v, hs, ls);
    const size_t o = (size_t)z * 4096 * 1024 + idx4;
    *reinterpret_cast<ushort4*>(&g_ahi[o]) = hs;
    *reinterpret_cast<ushort4*>(&g_alo[o]) = ls;
}

__global__ __launch_bounds__(256)
void convert_w_kernel(const float* __restrict__ ipw, const float* __restrict__ opw)
{
    const size_t idx4 = ((size_t)blockIdx.x * 256 + threadIdx.x) * 4;
    const size_t r = idx4 >> 10;
    const size_t e = idx4 & 1023;
    const float* src = (r < 3072) ? (ipw + idx4) : (opw + ((r - 3072) << 10) + e);
    float4 v = *reinterpret_cast<const float4*>(src);
    ushort4 hs, ls;
    split4(v, hs, ls);
    *reinterpret_cast<ushort4*>(&g_whi[idx4]) = hs;
    *reinterpret_cast<ushort4*>(&g_wlo[idx4]) = ls;
}

// ---------------------------------------------------------------------------
// proj GEMM (HMMA 3xBF16, cp.async double-buffered, pre-split bf16 operands)
// C[128x128] = A[M,1024] @ W[N,1024]^T + bias
// outmode=0, grid.z=z: A = g_ahi/g_alo[z], W = g_whi/g_wlo[z], epilogue ->
//   split bf16 scatter into (g_qhi,g_qlo)/(g_khi,g_klo)/(g_vhi,g_vlo) (B,H,T,D)
// outmode=3: A = g_chi/g_clo, W = slot 3, epilogue -> f32 outPlain
// ---------------------------------------------------------------------------
#define KT 64
#define LDP 72   // 64 halfs + 8 pad (144 B rows, conflict-free ldmatrix)
#define TILE_HALFS (128 * LDP)
#define PROJ_SMEM (2 * 4 * TILE_HALFS * 2)   // 147456 B

__global__ __launch_bounds__(256, 1)
void proj_mma_kernel(const float* __restrict__ biasBase,
                     float* __restrict__ outPlain,
                     int outmode)
{
    extern __shared__ __nv_bfloat16 dynsm[];
    const uint32_t ubase = smem_u32(dynsm);

    const int tid = threadIdx.x;
    const int lane = tid & 31, wid = tid >> 5;
    const int wm = wid >> 1, wn = wid & 1;     // 4x2 warps: 32x64 each
    const int z = (outmode == 3) ? 3 : blockIdx.z;

    const __nv_bfloat16 *Ah, *Al;
    if (outmode == 3) { Ah = g_chi; Al = g_clo; }
    else {
        Ah = g_ahi + (size_t)z * 4096 * 1024;
        Al = g_alo + (size_t)z * 4096 * 1024;
    }
    const __nv_bfloat16* Wh = g_whi + (size_t)z * 1024 * 1024;
    const __nv_bfloat16* Wl = g_wlo + (size_t)z * 1024 * 1024;
    const float* bias = biasBase + (outmode == 3 ? 0 : z * 1024);

    const int row0 = blockIdx.y * 128;
    const int col0 = blockIdx.x * 128;

    const __nv_bfloat16* gbase[4] = {
        Ah + (size_t)row0 * 1024, Al + (size_t)row0 * 1024,
        Wh + (size_t)col0 * 1024, Wl + (size_t)col0 * 1024
    };

    float acc[2][8][4];
#pragma unroll
    for (int i = 0; i < 2; i++)
#pragma unroll
        for (int j = 0; j < 8; j++)
#pragma unroll
            for (int k = 0; k < 4; k++) acc[i][j][k] = 0.0f;

    // stage kt into buffer buf: 4 ops x 128 rows x 8 chunks = 4096 cp.async
    auto stage = [&](int kt, int buf) {
#pragma unroll
        for (int i = 0; i < 16; i++) {
            const int idx = tid + i * 256;         // 0..4095
            const int op = idx >> 10;
            const int c = idx & 1023;
            const int row = c >> 3, kc = c & 7;
            const __nv_bfloat16* src = gbase[op] + (size_t)row * 1024 + kt * KT + kc * 8;
            const uint32_t dst = ubase +
                ((uint32_t)(buf * 4 + op) * TILE_HALFS + row * LDP + kc * 8) * 2u;
            cp16(dst, src);
        }
    };

    stage(0, 0);
    CP_COMMIT();

    const int NKT = 1024 / KT;   // 16
    for (int kt = 0; kt < NKT; kt++) {
        if (kt + 1 < NKT) {
            stage(kt + 1, (kt + 1) & 1);
            CP_COMMIT();
            CP_WAIT1();
        } else {
            CP_WAIT0();
        }
        __syncthreads();

        const int buf = kt & 1;
        const uint32_t uAh = ubase + (uint32_t)(buf * 4 + 0) * TILE_HALFS * 2u;
        const uint32_t uAl = ubase + (uint32_t)(buf * 4 + 1) * TILE_HALFS * 2u;
        const uint32_t uBh = ubase + (uint32_t)(buf * 4 + 2) * TILE_HALFS * 2u;
        const uint32_t uBl = ubase + (uint32_t)(buf * 4 + 3) * TILE_HALFS * 2u;

#pragma unroll
        for (int ks = 0; ks < KT; ks += 16) {
            uint32_t ah[2][4], al[2][4], bh2[8][2], bl2[8][2];
#pragma unroll
            for (int mt = 0; mt < 2; mt++) {
                load_a_frag(ah[mt], uAh, wm * 32 + mt * 16, ks, lane, LDP);
                load_a_frag(al[mt], uAl, wm * 32 + mt * 16, ks, lane, LDP);
            }
#pragma unroll
            for (int p = 0; p < 4; p++) {
                load_b_frag2(bh2[2 * p], bh2[2 * p + 1], uBh, wn * 64 + p * 16, ks, lane, LDP);
                load_b_frag2(bl2[2 * p], bl2[2 * p + 1], uBl, wn * 64 + p * 16, ks, lane, LDP);
            }
#pragma unroll
            for (int mt = 0; mt < 2; mt++)
#pragma unroll
                for (int nt = 0; nt < 8; nt++) {
                    mma16816(acc[mt][nt], ah[mt], bh2[nt]);
                    mma16816(acc[mt][nt], ah[mt], bl2[nt]);
                    mma16816(acc[mt][nt], al[mt], bh2[nt]);
                }
        }
        __syncthreads();
    }

    // epilogue
    __nv_bfloat16* dsthi = (z == 0) ? g_qhi : (z == 1) ? g_khi : g_vhi;
    __nv_bfloat16* dstlo = (z == 0) ? g_qlo : (z == 1) ? g_klo : g_vlo;
#pragma unroll
    for (int mt = 0; mt < 2; mt++) {
#pragma unroll
        for (int nt = 0; nt < 8; nt++) {
            const int n = col0 + wn * 64 + nt * 8 + 2 * (lane & 3);
            const float b0 = bias[n], b1 = bias[n + 1];
#pragma unroll
            for (int half = 0; half < 2; half++) {
                const int m = row0 + wm * 32 + mt * 16 + (lane >> 2) + half * 8;
                const float v0 = acc[mt][nt][2 * half + 0] + b0;
                const float v1 = acc[mt][nt][2 * half + 1] + b1;
                if (outmode == 3) {
                    *reinterpret_cast<float2*>(&outPlain[(size_t)m * Ee + n]) =
                        make_float2(v0, v1);
                } else {
                    const int bidx = m >> 11, t = m & 2047;
                    const int h = n >> 6, d = n & 63;
                    const size_t o = (((size_t)bidx * Hh + h) * Tt + t) * Dd + d;
                    uint32_t hi, lo;
                    split2(v0, v1, hi, lo);
                    *reinterpret_cast<uint32_t*>(&dsthi[o]) = hi;
                    *reinterpret_cast<uint32_t*>(&dstlo[o]) = lo;
                }
            }
        }
    }
}

// ---------------------------------------------------------------------------
// scores (HMMA 3xBF16) — unchanged, validated (reads g_qhi/g_klo splits)
// ---------------------------------------------------------------------------
#define LDSA 40

__global__ __launch_bounds__(256, 1)
void scores_mma_kernel()
{
    __shared__ __align__(16) __nv_bfloat16 sAh[128 * LDSA], sAl[128 * LDSA];
    __shared__ __align__(16) __nv_bfloat16 sBh[128 * LDSA], sBl[128 * LDSA];

    const int tid = threadIdx.x;
    const int lane = tid & 31, wid = tid >> 5;
    const int wm = wid >> 1, wn = wid & 1;
    const int bh = blockIdx.z;
    const size_t base = (size_t)bh * Tt * Dd;
    const int row0 = blockIdx.y * 128;
    const int col0 = blockIdx.x * 128;

    const uint32_t uAh = smem_u32(sAh), uAl = smem_u32(sAl);
    const uint32_t uBh = smem_u32(sBh), uBl = smem_u32(sBl);

    float acc[2][8][4];
#pragma unroll
    for (int i = 0; i < 2; i++)
#pragma unroll
        for (int j = 0; j < 8; j++)
#pragma unroll
            for (int k = 0; k < 4; k++) acc[i][j][k] = 0.0f;

    for (int k0 = 0; k0 < 64; k0 += 32) {
#pragma unroll
        for (int c = 0; c < 2; c++) {
            const int ch = tid + c * 256;
            const int row = ch >> 2, kc = ch & 3;
            const size_t ga = base + (size_t)(row0 + row) * 64 + k0 + kc * 8;
            const size_t gb = base + (size_t)(col0 + row) * 64 + k0 + kc * 8;
            const int so = row * LDSA + kc * 8;
            *reinterpret_cast<uint4*>(&sAh[so]) = *reinterpret_cast<const uint4*>(&g_qhi[ga]);
            *reinterpret_cast<uint4*>(&sAl[so]) = *reinterpret_cast<const uint4*>(&g_qlo[ga]);
            *reinterpret_cast<uint4*>(&sBh[so]) = *reinterpret_cast<const uint4*>(&g_khi[gb]);
            *reinterpret_cast<uint4*>(&sBl[so]) = *reinterpret_cast<const uint4*>(&g_klo[gb]);
        }
        __syncthreads();

#pragma unroll
        for (int ks = 0; ks < 32; ks += 16) {
            uint32_t ah[2][4], al[2][4], bh2[8][2], bl2[8][2];
#pragma unroll
            for (int mt = 0; mt < 2; mt++) {
                load_a_frag(ah[mt], uAh, wm * 32 + mt * 16, ks, lane, LDSA);
                load_a_frag(al[mt], uAl, wm * 32 + mt * 16, ks, lane, LDSA);
            }
#pragma unroll
            for (int p = 0; p < 4; p++) {
                load_b_frag2(bh2[2 * p], bh2[2 * p + 1], uBh, wn * 64 + p * 16, ks, lane, LDSA);
                load_b_frag2(bl2[2 * p], bl2[2 * p + 1], uBl, wn * 64 + p * 16, ks, lane, LDSA);
            }
#pragma unroll
            for (int mt = 0; mt < 2; mt++)
#pragma unroll
                for (int nt = 0; nt < 8; nt++) {
                    mma16816(acc[mt][nt], ah[mt], bh2[nt]);
                    mma16816(acc[mt][nt], ah[mt], bl2[nt]);
                    mma16816(acc[mt][nt], al[mt], bh2[nt]);
                }
        }
        __syncthreads();
    }

    float* C = g_attn + (size_t)bh * Tt * Ss;
#pragma unroll
    for (int mt = 0; mt < 2; mt++)
#pragma unroll
        for (int nt = 0; nt < 8; nt++) {
            const int n = col0 + wn * 64 + nt * 8 + 2 * (lane & 3);
#pragma unroll
            for (int half = 0; half < 2; half++) {
                const int m = row0 + wm * 32 + mt * 16 + (lane >> 2) + half * 8;
                *reinterpret_cast<float2*>(&C[(size_t)m * Ss + n]) =
                    make_float2(acc[mt][nt][2 * half] * 0.125f,
                                acc[mt][nt][2 * half + 1] * 0.125f);
            }
        }
}

// ---------------------------------------------------------------------------
// softmax: f32 scores in, split bf16 probs out (g_phi/g_plo) + head-mean
// ---------------------------------------------------------------------------
__global__ __launch_bounds__(256)
void softmax_kernel(float* __restrict__ wout)
{
    const int bt = blockIdx.x;
    const int b = bt / Tt, t = bt % Tt;
    const int tid = threadIdx.x;

    __shared__ float red[256];

    float wsum[8];
#pragma unroll
    for (int i = 0; i < 8; i++) wsum[i] = 0.0f;

    for (int h = 0; h < Hh; h++) {
        const size_t rowoff = (((size_t)b * Hh + h) * Tt + t) * Ss;
        const float* arow = g_attn + rowoff;
        float lv[8];
        float lmax = -1e30f;
#pragma unroll
        for (int i = 0; i < 8; i++) {
            lv[i] = arow[tid + i * 256];
            lmax = fmaxf(lmax, lv[i]);
        }
        red[tid] = lmax;
        __syncthreads();
        for (int s = 128; s > 0; s >>= 1) {
            if (tid < s) red[tid] = fmaxf(red[tid], red[tid + s]);
            __syncthreads();
        }
        const float m = red[0];
        __syncthreads();
        float lsum = 0.0f;
#pragma unroll
        for (int i = 0; i < 8; i++) {
            lv[i] = __expf(lv[i] - m);
            lsum += lv[i];
        }
        red[tid] = lsum;
        __syncthreads();
        for (int s = 128; s > 0; s >>= 1) {
            if (tid < s) red[tid] += red[tid + s];
            __syncthreads();
        }
        const float inv = 1.0f / red[0];
        __syncthreads();
#pragma unroll
        for (int i = 0; i < 8; i++) {
            const float p = lv[i] * inv;
            const __nv_bfloat16 ph = __float2bfloat16(p);
            const __nv_bfloat16 pl = __float2bfloat16(p - __bfloat162float(ph));
            g_phi[rowoff + tid + i * 256] = ph;
            g_plo[rowoff + tid + i * 256] = pl;
            wsum[i] += p * (1.0f / Hh);
        }
    }
#pragma unroll
    for (int i = 0; i < 8; i++)
        wout[(size_t)bt * Ss + tid + i * 256] = wsum[i];
}

// ---------------------------------------------------------------------------
// ctx (HMMA 3xBF16): [128,64] = P[128,2048] @ V[2048,64]; pure-copy staging
// from pre-split g_phi/g_plo and g_vhi/g_vlo; writes split g_chi/g_clo.
// ---------------------------------------------------------------------------
#define LDSV 72

__global__ __launch_bounds__(256, 1)
void ctx_mma_kernel()
{
    __shared__ __align__(16) __nv_bfloat16 sPh[128 * LDSA], sPl[128 * LDSA];
    __shared__ __align__(16) __nv_bfloat16 sVh[32 * LDSV],  sVl[32 * LDSV];

    const int tid = threadIdx.x;
    const int lane = tid & 31, wid = tid >> 5;
    const int bh = blockIdx.z;
    const int b = bh >> 4, h = bh & 15;
    const int row0 = blockIdx.y * 128;
    const size_t pbase = (size_t)bh * Tt * Ss;
    const size_t vbase = (size_t)bh * Ss * Dd;

    const uint32_t uPh = smem_u32(sPh), uPl = smem_u32(sPl);
    const uint32_t uVh = smem_u32(sVh), uVl = smem_u32(sVl);

    float acc[8][4];
#pragma unroll
    for (int j = 0; j < 8; j++)
#pragma unroll
        for (int k = 0; k < 4; k++) acc[j][k] = 0.0f;

    for (int k0 = 0; k0 < Ss; k0 += 32) {
        // P tile 128x32 bf16 hi/lo: 512 16B-chunks per array, 2/thread
#pragma unroll
        for (int c = 0; c < 2; c++) {
            const int ch = tid + c * 256;          // 0..511
            const int row = ch >> 2, kc = ch & 3;  // 4 chunks/row (8 halfs each)
            const size_t gp = pbase + (size_t)(row0 + row) * Ss + k0 + kc * 8;
            const int so = row * LDSA + kc * 8;
            *reinterpret_cast<uint4*>(&sPh[so]) = *reinterpret_cast<const uint4*>(&g_phi[gp]);
            *reinterpret_cast<uint4*>(&sPl[so]) = *reinterpret_cast<const uint4*>(&g_plo[gp]);
        }
        // V tile 32x64 bf16 hi/lo: 256 chunks per array, 1/thread
        {
            const int row = tid >> 3, dc = tid & 7;  // 8 chunks/row
            const size_t gv = vbase + (size_t)(k0 + row) * Dd + dc * 8;
            const int so = row * LDSV + dc * 8;
            *reinterpret_cast<uint4*>(&sVh[so]) = *reinterpret_cast<const uint4*>(&g_vhi[gv]);
            *reinterpret_cast<uint4*>(&sVl[so]) = *reinterpret_cast<const uint4*>(&g_vlo[gv]);
        }
        __syncthreads();

#pragma unroll
        for (int ks = 0; ks < 32; ks += 16) {
            uint32_t ah[4], al[4], bh2[8][2], bl2[8][2];
            load_a_frag(ah, uPh, wid * 16, ks, lane, LDSA);
            load_a_frag(al, uPl, wid * 16, ks, lane, LDSA);
#pragma unroll
            for (int p = 0; p < 4; p++) {
                load_b_frag2_trans(bh2[2 * p], bh2[2 * p + 1], uVh, p * 16, ks, lane, LDSV);
                load_b_frag2_trans(bl2[2 * p], bl2[2 * p + 1], uVl, p * 16, ks, lane, LDSV);
            }
#pragma unroll
            for (int nt = 0; nt < 8; nt++) {
                mma16816(acc[nt], ah, bh2[nt]);
                mma16816(acc[nt], ah, bl2[nt]);
                mma16816(acc[nt], al, bh2[nt]);
            }
        }
        __syncthreads();
    }

    // epilogue: split ctx into g_chi/g_clo at (b, t, h*64 + d)
#pragma unroll
    for (int nt = 0; nt < 8; nt++) {
        const int d = nt * 8 + 2 * (lane & 3);
#pragma unroll
        for (int half = 0; half < 2; half++) {
            const int t = row0 + wid * 16 + (lane >> 2) + half * 8;
            const size_t o = ((size_t)b * Tt + t) * Ee + h * Dd + d;
            uint32_t hi, lo;
            split2(acc[nt][2 * half], acc[nt][2 * half + 1], hi, lo);
            *reinterpret_cast<uint32_t*>(&g_chi[o]) = hi;
            *reinterpret_cast<uint32_t*>(&g_clo[o]) = lo;
        }
    }
}

// ---------------------------------------------------------------------------
extern "C" void kernel_launch(void* const* d_in, const int* in_sizes, int n_in,
                              void* d_out, int out_size)
{
    const float* q    = (const float*)d_in[0];
    const float* kv   = (const float*)d_in[1];
    const float* ipw  = (const float*)d_in[2];
    const float* ipb  = (const float*)d_in[3];
    const float* opw  = (const float*)d_in[4];
    const float* opb  = (const float*)d_in[5];
    float* out = (float*)d_out;                       // (B,T,H,D) flattened
    float* wout = out + (size_t)Bb * Tt * Ee;         // (B,T,S) flattened

    cudaFuncSetAttribute(proj_mma_kernel,
                         cudaFuncAttributeMaxDynamicSharedMemorySize, PROJ_SMEM);

    // 0. split conversions (weights + activations)
    convert_qkv_kernel<<<dim3(4096, 1, 3), 256>>>(q, kv);
    convert_w_kernel<<<4096, 256>>>(ipw, opw);

    // 1. QKV projections -> split bf16 Q/K/V operands
    proj_mma_kernel<<<dim3(8, 32, 3), 256, PROJ_SMEM>>>(ipb, nullptr, 0);

    // 2. scores -> f32 g_attn
    scores_mma_kernel<<<dim3(16, 16, Bb * Hh), 256>>>();

    // 3. softmax -> split bf16 probs + head-mean wout
    softmax_kernel<<<Bb * Tt, 256>>>(wout);

    // 4. ctx = P @ V -> split bf16 g_chi/g_clo
    ctx_mma_kernel<<<dim3(1, 16, Bb * Hh), 256>>>();

    // 5. out projection -> f32 d_out
    proj_mma_kernel<<<dim3(8, 32, 1), 256, PROJ_SMEM>>>(opb, out, 3);
}

// round 16
// speedup vs baseline: 2.8341x; 1.1164x over previous
#include <cuda_runtime.h>
#include <cuda_bf16.h>
#include <cstdint>
#include <math.h>

#define Bb 2
#define Tt 2048
#define Ss 2048
#define Hh 16
#define Dd 64
#define Ee 1024

// ---------------------------------------------------------------------------
// Scratch (static __device__). Referenced ONLY from device code — never passed
// as kernel arguments from host (R7/R11 root cause).
// ---------------------------------------------------------------------------
__device__ float g_attn[(size_t)Bb * Hh * Tt * Ss];        // f32 scores (512 MB)

__device__ __nv_bfloat16 g_ahi[(size_t)3 * 4096 * 1024];   // qkv activations split
__device__ __nv_bfloat16 g_alo[(size_t)3 * 4096 * 1024];
__device__ __nv_bfloat16 g_whi[(size_t)4 * 1024 * 1024];   // in_proj(3)+out_proj(1)
__device__ __nv_bfloat16 g_wlo[(size_t)4 * 1024 * 1024];

#define PROJ_ELEMS ((size_t)Bb * Hh * Tt * Dd)
__device__ __nv_bfloat16 g_qhi[PROJ_ELEMS], g_qlo[PROJ_ELEMS];
__device__ __nv_bfloat16 g_khi[PROJ_ELEMS], g_klo[PROJ_ELEMS];
__device__ __nv_bfloat16 g_vhi[PROJ_ELEMS], g_vlo[PROJ_ELEMS];

__device__ __nv_bfloat16 g_phi[(size_t)Bb * Hh * Tt * Ss]; // softmax probs split
__device__ __nv_bfloat16 g_plo[(size_t)Bb * Hh * Tt * Ss];

__device__ __nv_bfloat16 g_chi[(size_t)4096 * 1024];       // ctx split
__device__ __nv_bfloat16 g_clo[(size_t)4096 * 1024];

// ---------------------------------------------------------------------------
// Primitives
// ---------------------------------------------------------------------------
__device__ __forceinline__ uint32_t smem_u32(const void* p) {
    uint32_t a;
    asm("{ .reg .u64 t; cvta.to.shared.u64 t, %1; cvt.u32.u64 %0, t; }"
        : "=r"(a) : "l"(p));
    return a;
}

__device__ __forceinline__ void mma16816(float* d, const uint32_t* a, const uint32_t* b) {
    asm volatile(
        "mma.sync.aligned.m16n8k16.row.col.f32.bf16.bf16.f32 "
        "{%0,%1,%2,%3}, {%4,%5,%6,%7}, {%8,%9}, {%0,%1,%2,%3};"
        : "+f"(d[0]), "+f"(d[1]), "+f"(d[2]), "+f"(d[3])
        : "r"(a[0]), "r"(a[1]), "r"(a[2]), "r"(a[3]), "r"(b[0]), "r"(b[1]));
}

#define LDSM4(R0,R1,R2,R3,ADDR) \
    asm volatile("ldmatrix.sync.aligned.m8n8.x4.shared.b16 {%0,%1,%2,%3}, [%4];" \
        : "=r"(R0),"=r"(R1),"=r"(R2),"=r"(R3) : "r"(ADDR))
#define LDSM4T(R0,R1,R2,R3,ADDR) \
    asm volatile("ldmatrix.sync.aligned.m8n8.x4.trans.shared.b16 {%0,%1,%2,%3}, [%4];" \
        : "=r"(R0),"=r"(R1),"=r"(R2),"=r"(R3) : "r"(ADDR))

__device__ __forceinline__ void load_a_frag(uint32_t* fr, uint32_t base_u32,
                                            int mbase, int ks, int lane, int lds) {
    const int row = mbase + (lane & 15);
    const int col = ks + ((lane >> 4) << 3);
    LDSM4(fr[0], fr[1], fr[2], fr[3], base_u32 + (uint32_t)(row * lds + col) * 2u);
}
__device__ __forceinline__ void load_b_frag2(uint32_t* f0, uint32_t* f1, uint32_t base_u32,
                                             int nb, int ks, int lane, int lds) {
    const int g = lane >> 3, r = lane & 7;
    const int row = nb + ((g >> 1) << 3) + r;
    const int col = ks + ((g & 1) << 3);
    LDSM4(f0[0], f0[1], f1[0], f1[1], base_u32 + (uint32_t)(row * lds + col) * 2u);
}
__device__ __forceinline__ void load_b_frag2_trans(uint32_t* f0, uint32_t* f1, uint32_t base_u32,
                                                   int db, int ks, int lane, int lds) {
    const int g = lane >> 3, r = lane & 7;
    const int row = ks + ((g & 1) << 3) + r;
    const int col = db + ((g >> 1) << 3);
    LDSM4T(f0[0], f0[1], f1[0], f1[1], base_u32 + (uint32_t)(row * lds + col) * 2u);
}

__device__ __forceinline__ void cp16(uint32_t saddr, const void* gptr) {
    asm volatile("cp.async.cg.shared.global [%0], [%1], 16;"
                 :: "r"(saddr), "l"(gptr));
}
#define CP_COMMIT() asm volatile("cp.async.commit_group;" ::: "memory")
#define CP_WAIT1()  asm volatile("cp.async.wait_group 1;" ::: "memory")
#define CP_WAIT0()  asm volatile("cp.async.wait_group 0;" ::: "memory")

__device__ __forceinline__ void split4(float4 v, ushort4& hs, ushort4& ls)
{
    __nv_bfloat16 h0 = __float2bfloat16(v.x);
    __nv_bfloat16 h1 = __float2bfloat16(v.y);
    __nv_bfloat16 h2 = __float2bfloat16(v.z);
    __nv_bfloat16 h3 = __float2bfloat16(v.w);
    __nv_bfloat16 l0 = __float2bfloat16(v.x - __bfloat162float(h0));
    __nv_bfloat16 l1 = __float2bfloat16(v.y - __bfloat162float(h1));
    __nv_bfloat16 l2 = __float2bfloat16(v.z - __bfloat162float(h2));
    __nv_bfloat16 l3 = __float2bfloat16(v.w - __bfloat162float(h3));
    hs = make_ushort4(__bfloat16_as_ushort(h0), __bfloat16_as_ushort(h1),
                      __bfloat16_as_ushort(h2), __bfloat16_as_ushort(h3));
    ls = make_ushort4(__bfloat16_as_ushort(l0), __bfloat16_as_ushort(l1),
                      __bfloat16_as_ushort(l2), __bfloat16_as_ushort(l3));
}
__device__ __forceinline__ void split2(float a, float b, uint32_t& hi, uint32_t& lo) {
    __nv_bfloat16 ha = __float2bfloat16(a), hb = __float2bfloat16(b);
    hi = ((uint32_t)__bfloat16_as_ushort(hb) << 16) | __bfloat16_as_ushort(ha);
    __nv_bfloat16 la = __float2bfloat16(a - __bfloat162float(ha));
    __nv_bfloat16 lb = __float2bfloat16(b - __bfloat162float(hb));
    lo = ((uint32_t)__bfloat16_as_ushort(lb) << 16) | __bfloat16_as_ushort(la);
}

// ---------------------------------------------------------------------------
// Conversion kernels (validated)
// ---------------------------------------------------------------------------
__global__ __launch_bounds__(256)
void convert_qkv_kernel(const float* __restrict__ q, const float* __restrict__ kv)
{
    const int z = blockIdx.z;
    const size_t idx4 = ((size_t)blockIdx.x * 256 + threadIdx.x) * 4;
    const size_t m = idx4 >> 10;
    const size_t e = idx4 & 1023;
    const float* src;
    if (z == 0)      src = q  + m * 1024 + e;
    else if (z == 1) src = kv + m * 2048 + e;
    else             src = kv + m * 2048 + 1024 + e;
    float4 v = *reinterpret_cast<const float4*>(src);
    ushort4 hs, ls;
    split4(v, hs, ls);
    const size_t o = (size_t)z * 4096 * 1024 + idx4;
    *reinterpret_cast<ushort4*>(&g_ahi[o]) = hs;
    *reinterpret_cast<ushort4*>(&g_alo[o]) = ls;
}

__global__ __launch_bounds__(256)
void convert_w_kernel(const float* __restrict__ ipw, const float* __restrict__ opw)
{
    const size_t idx4 = ((size_t)blockIdx.x * 256 + threadIdx.x) * 4;
    const size_t r = idx4 >> 10;
    const size_t e = idx4 & 1023;
    const float* src = (r < 3072) ? (ipw + idx4) : (opw + ((r - 3072) << 10) + e);
    float4 v = *reinterpret_cast<const float4*>(src);
    ushort4 hs, ls;
    split4(v, hs, ls);
    *reinterpret_cast<ushort4*>(&g_whi[idx4]) = hs;
    *reinterpret_cast<ushort4*>(&g_wlo[idx4]) = ls;
}

// ---------------------------------------------------------------------------
// proj GEMM (HMMA 3xBF16, cp.async double-buffered) — unchanged, validated
// ---------------------------------------------------------------------------
#define KT 64
#define LDP 72
#define TILE_HALFS (128 * LDP)
#define PROJ_SMEM (2 * 4 * TILE_HALFS * 2)

__global__ __launch_bounds__(256, 1)
void proj_mma_kernel(const float* __restrict__ biasBase,
                     float* __restrict__ outPlain,
                     int outmode)
{
    extern __shared__ __nv_bfloat16 dynsm[];
    const uint32_t ubase = smem_u32(dynsm);

    const int tid = threadIdx.x;
    const int lane = tid & 31, wid = tid >> 5;
    const int wm = wid >> 1, wn = wid & 1;
    const int z = (outmode == 3) ? 3 : blockIdx.z;

    const __nv_bfloat16 *Ah, *Al;
    if (outmode == 3) { Ah = g_chi; Al = g_clo; }
    else {
        Ah = g_ahi + (size_t)z * 4096 * 1024;
        Al = g_alo + (size_t)z * 4096 * 1024;
    }
    const __nv_bfloat16* Wh = g_whi + (size_t)z * 1024 * 1024;
    const __nv_bfloat16* Wl = g_wlo + (size_t)z * 1024 * 1024;
    const float* bias = biasBase + (outmode == 3 ? 0 : z * 1024);

    const int row0 = blockIdx.y * 128;
    const int col0 = blockIdx.x * 128;

    const __nv_bfloat16* gbase[4] = {
        Ah + (size_t)row0 * 1024, Al + (size_t)row0 * 1024,
        Wh + (size_t)col0 * 1024, Wl + (size_t)col0 * 1024
    };

    float acc[2][8][4];
#pragma unroll
    for (int i = 0; i < 2; i++)
#pragma unroll
        for (int j = 0; j < 8; j++)
#pragma unroll
            for (int k = 0; k < 4; k++) acc[i][j][k] = 0.0f;

    auto stage = [&](int kt, int buf) {
#pragma unroll
        for (int i = 0; i < 16; i++) {
            const int idx = tid + i * 256;
            const int op = idx >> 10;
            const int c = idx & 1023;
            const int row = c >> 3, kc = c & 7;
            const __nv_bfloat16* src = gbase[op] + (size_t)row * 1024 + kt * KT + kc * 8;
            const uint32_t dst = ubase +
                ((uint32_t)(buf * 4 + op) * TILE_HALFS + row * LDP + kc * 8) * 2u;
            cp16(dst, src);
        }
    };

    stage(0, 0);
    CP_COMMIT();

    const int NKT = 1024 / KT;
    for (int kt = 0; kt < NKT; kt++) {
        if (kt + 1 < NKT) {
            stage(kt + 1, (kt + 1) & 1);
            CP_COMMIT();
            CP_WAIT1();
        } else {
            CP_WAIT0();
        }
        __syncthreads();

        const int buf = kt & 1;
        const uint32_t uAh = ubase + (uint32_t)(buf * 4 + 0) * TILE_HALFS * 2u;
        const uint32_t uAl = ubase + (uint32_t)(buf * 4 + 1) * TILE_HALFS * 2u;
        const uint32_t uBh = ubase + (uint32_t)(buf * 4 + 2) * TILE_HALFS * 2u;
        const uint32_t uBl = ubase + (uint32_t)(buf * 4 + 3) * TILE_HALFS * 2u;

#pragma unroll
        for (int ks = 0; ks < KT; ks += 16) {
            uint32_t ah[2][4], al[2][4], bh2[8][2], bl2[8][2];
#pragma unroll
            for (int mt = 0; mt < 2; mt++) {
                load_a_frag(ah[mt], uAh, wm * 32 + mt * 16, ks, lane, LDP);
                load_a_frag(al[mt], uAl, wm * 32 + mt * 16, ks, lane, LDP);
            }
#pragma unroll
            for (int p = 0; p < 4; p++) {
                load_b_frag2(bh2[2 * p], bh2[2 * p + 1], uBh, wn * 64 + p * 16, ks, lane, LDP);
                load_b_frag2(bl2[2 * p], bl2[2 * p + 1], uBl, wn * 64 + p * 16, ks, lane, LDP);
            }
#pragma unroll
            for (int mt = 0; mt < 2; mt++)
#pragma unroll
                for (int nt = 0; nt < 8; nt++) {
                    mma16816(acc[mt][nt], ah[mt], bh2[nt]);
                    mma16816(acc[mt][nt], ah[mt], bl2[nt]);
                    mma16816(acc[mt][nt], al[mt], bh2[nt]);
                }
        }
        __syncthreads();
    }

    __nv_bfloat16* dsthi = (z == 0) ? g_qhi : (z == 1) ? g_khi : g_vhi;
    __nv_bfloat16* dstlo = (z == 0) ? g_qlo : (z == 1) ? g_klo : g_vlo;
#pragma unroll
    for (int mt = 0; mt < 2; mt++) {
#pragma unroll
        for (int nt = 0; nt < 8; nt++) {
            const int n = col0 + wn * 64 + nt * 8 + 2 * (lane & 3);
            const float b0 = bias[n], b1 = bias[n + 1];
#pragma unroll
            for (int half = 0; half < 2; half++) {
                const int m = row0 + wm * 32 + mt * 16 + (lane >> 2) + half * 8;
                const float v0 = acc[mt][nt][2 * half + 0] + b0;
                const float v1 = acc[mt][nt][2 * half + 1] + b1;
                if (outmode == 3) {
                    *reinterpret_cast<float2*>(&outPlain[(size_t)m * Ee + n]) =
                        make_float2(v0, v1);
                } else {
                    const int bidx = m >> 11, t = m & 2047;
                    const int h = n >> 6, d = n & 63;
                    const size_t o = (((size_t)bidx * Hh + h) * Tt + t) * Dd + d;
                    uint32_t hi, lo;
                    split2(v0, v1, hi, lo);
                    *reinterpret_cast<uint32_t*>(&dsthi[o]) = hi;
                    *reinterpret_cast<uint32_t*>(&dstlo[o]) = lo;
                }
            }
        }
    }
}

// ---------------------------------------------------------------------------
// scores v2 (HMMA 3xBF16): per CTA: one Q row-tile, 4 K column tiles,
// cp.async prefetch of next K tile overlapped with current MMA + store.
// smem halfs layout: Qh 0, Ql 9216, K[buf] hi 18432+buf*18432, lo +9216.
// ---------------------------------------------------------------------------
#define SC_TILE (128 * LDP)              // 9216 halfs
#define SC_SMEM ((2 + 4) * SC_TILE * 2)  // 110592 B

__global__ __launch_bounds__(256, 1)
void scores_mma_kernel()
{
    extern __shared__ __nv_bfloat16 dynsm[];
    const uint32_t ubase = smem_u32(dynsm);

    const int tid = threadIdx.x;
    const int lane = tid & 31, wid = tid >> 5;
    const int wm = wid >> 1, wn = wid & 1;
    const int bh = blockIdx.z;
    const size_t base = (size_t)bh * Tt * Dd;
    const int row0 = blockIdx.y * 128;
    const int colg = blockIdx.x * 4;     // 4 column tiles per CTA

    // stage Q tile (hi+lo): 2048 cp16
    {
        const __nv_bfloat16* qsrc[2] = { g_qhi + base + (size_t)row0 * 64,
                                         g_qlo + base + (size_t)row0 * 64 };
#pragma unroll
        for (int i = 0; i < 8; i++) {
            const int idx = tid + i * 256;       // 0..2047
            const int op = idx >> 10;
            const int c = idx & 1023;
            const int row = c >> 3, kc = c & 7;
            cp16(ubase + ((uint32_t)op * SC_TILE + row * LDP + kc * 8) * 2u,
                 qsrc[op] + (size_t)row * 64 + kc * 8);
        }
    }
    // stage K tile for column tile ct into buffer b
    auto stage_k = [&](int ct, int b) {
        const int col0 = (colg + ct) * 128;
        const __nv_bfloat16* ksrc[2] = { g_khi + base + (size_t)col0 * 64,
                                         g_klo + base + (size_t)col0 * 64 };
#pragma unroll
        for (int i = 0; i < 8; i++) {
            const int idx = tid + i * 256;
            const int op = idx >> 10;
            const int c = idx & 1023;
            const int row = c >> 3, kc = c & 7;
            cp16(ubase + ((uint32_t)(2 + b * 2 + op) * SC_TILE + row * LDP + kc * 8) * 2u,
                 ksrc[op] + (size_t)row * 64 + kc * 8);
        }
    };

    stage_k(0, 0);
    CP_COMMIT();      // group: Q + K0

    const uint32_t uQh = ubase;
    const uint32_t uQl = ubase + (uint32_t)SC_TILE * 2u;

    for (int ct = 0; ct < 4; ct++) {
        if (ct < 3) {
            stage_k(ct + 1, (ct + 1) & 1);
            CP_COMMIT();
            CP_WAIT1();
        } else {
            CP_WAIT0();
        }
        __syncthreads();

        const int buf = ct & 1;
        const uint32_t uKh = ubase + (uint32_t)(2 + buf * 2) * SC_TILE * 2u;
        const uint32_t uKl = uKh + (uint32_t)SC_TILE * 2u;

        float acc[2][8][4];
#pragma unroll
        for (int i = 0; i < 2; i++)
#pragma unroll
            for (int j = 0; j < 8; j++)
#pragma unroll
                for (int k = 0; k < 4; k++) acc[i][j][k] = 0.0f;

#pragma unroll
        for (int ks = 0; ks < 64; ks += 16) {
            uint32_t ah[2][4], al[2][4], bh2[8][2], bl2[8][2];
#pragma unroll
            for (int mt = 0; mt < 2; mt++) {
                load_a_frag(ah[mt], uQh, wm * 32 + mt * 16, ks, lane, LDP);
                load_a_frag(al[mt], uQl, wm * 32 + mt * 16, ks, lane, LDP);
            }
#pragma unroll
            for (int p = 0; p < 4; p++) {
                load_b_frag2(bh2[2 * p], bh2[2 * p + 1], uKh, wn * 64 + p * 16, ks, lane, LDP);
                load_b_frag2(bl2[2 * p], bl2[2 * p + 1], uKl, wn * 64 + p * 16, ks, lane, LDP);
            }
#pragma unroll
            for (int mt = 0; mt < 2; mt++)
#pragma unroll
                for (int nt = 0; nt < 8; nt++) {
                    mma16816(acc[mt][nt], ah[mt], bh2[nt]);
                    mma16816(acc[mt][nt], ah[mt], bl2[nt]);
                    mma16816(acc[mt][nt], al[mt], bh2[nt]);
                }
        }

        // epilogue for this column tile
        float* C = g_attn + (size_t)bh * Tt * Ss;
        const int col0 = (colg + ct) * 128;
#pragma unroll
        for (int mt = 0; mt < 2; mt++)
#pragma unroll
            for (int nt = 0; nt < 8; nt++) {
                const int n = col0 + wn * 64 + nt * 8 + 2 * (lane & 3);
#pragma unroll
                for (int half = 0; half < 2; half++) {
                    const int m = row0 + wm * 32 + mt * 16 + (lane >> 2) + half * 8;
                    *reinterpret_cast<float2*>(&C[(size_t)m * Ss + n]) =
                        make_float2(acc[mt][nt][2 * half] * 0.125f,
                                    acc[mt][nt][2 * half + 1] * 0.125f);
                }
            }
        __syncthreads();   // buffer reuse guard
    }
}

// ---------------------------------------------------------------------------
// softmax: f32 scores in, split bf16 probs out + head-mean — unchanged
// ---------------------------------------------------------------------------
__global__ __launch_bounds__(256)
void softmax_kernel(float* __restrict__ wout)
{
    const int bt = blockIdx.x;
    const int b = bt / Tt, t = bt % Tt;
    const int tid = threadIdx.x;

    __shared__ float red[256];

    float wsum[8];
#pragma unroll
    for (int i = 0; i < 8; i++) wsum[i] = 0.0f;

    for (int h = 0; h < Hh; h++) {
        const size_t rowoff = (((size_t)b * Hh + h) * Tt + t) * Ss;
        const float* arow = g_attn + rowoff;
        float lv[8];
        float lmax = -1e30f;
#pragma unroll
        for (int i = 0; i < 8; i++) {
            lv[i] = arow[tid + i * 256];
            lmax = fmaxf(lmax, lv[i]);
        }
        red[tid] = lmax;
        __syncthreads();
        for (int s = 128; s > 0; s >>= 1) {
            if (tid < s) red[tid] = fmaxf(red[tid], red[tid + s]);
            __syncthreads();
        }
        const float m = red[0];
        __syncthreads();
        float lsum = 0.0f;
#pragma unroll
        for (int i = 0; i < 8; i++) {
            lv[i] = __expf(lv[i] - m);
            lsum += lv[i];
        }
        red[tid] = lsum;
        __syncthreads();
        for (int s = 128; s > 0; s >>= 1) {
            if (tid < s) red[tid] += red[tid + s];
            __syncthreads();
        }
        const float inv = 1.0f / red[0];
        __syncthreads();
#pragma unroll
        for (int i = 0; i < 8; i++) {
            const float p = lv[i] * inv;
            const __nv_bfloat16 ph = __float2bfloat16(p);
            const __nv_bfloat16 pl = __float2bfloat16(p - __bfloat162float(ph));
            g_phi[rowoff + tid + i * 256] = ph;
            g_plo[rowoff + tid + i * 256] = pl;
            wsum[i] += p * (1.0f / Hh);
        }
    }
#pragma unroll
    for (int i = 0; i < 8; i++)
        wout[(size_t)bt * Ss + tid + i * 256] = wsum[i];
}

// ---------------------------------------------------------------------------
// ctx v2 (HMMA 3xBF16): cp.async double-buffered staging over 64 k-iters.
// smem halfs per buffer: Ph 5120, Pl 5120, Vh 2304, Vl 2304 (block 14848).
// ---------------------------------------------------------------------------
#define LDSA 40
#define LDSV 72
#define CTX_PH  (128 * LDSA)             // 5120 halfs
#define CTX_VH  (32 * LDSV)              // 2304 halfs
#define CTX_BLK (2 * CTX_PH + 2 * CTX_VH)  // 14848 halfs
#define CTX_SMEM (2 * CTX_BLK * 2)       // 59392 B

__global__ __launch_bounds__(256, 1)
void ctx_mma_kernel()
{
    extern __shared__ __nv_bfloat16 dynsm[];
    const uint32_t ubase = smem_u32(dynsm);

    const int tid = threadIdx.x;
    const int lane = tid & 31, wid = tid >> 5;
    const int bh = blockIdx.z;
    const int b = bh >> 4, h = bh & 15;
    const int row0 = blockIdx.y * 128;
    const size_t pbase = (size_t)bh * Tt * Ss;
    const size_t vbase = (size_t)bh * Ss * Dd;

    float acc[8][4];
#pragma unroll
    for (int j = 0; j < 8; j++)
#pragma unroll
        for (int k = 0; k < 4; k++) acc[j][k] = 0.0f;

    // stage k-iter ki into buffer buf: P 1024 cp16 (4/thr) + V 512 cp16 (2/thr)
    auto stage = [&](int ki, int buf) {
        const int k0 = ki * 32;
        const uint32_t bofs = (uint32_t)buf * CTX_BLK;
#pragma unroll
        for (int c = 0; c < 2; c++) {
            const int ch = tid + c * 256;          // 0..511
            const int row = ch >> 2, kc = ch & 3;  // 4 chunks/row
            const size_t gp = pbase + (size_t)(row0 + row) * Ss + k0 + kc * 8;
            const uint32_t so = bofs + row * LDSA + kc * 8;
            cp16(ubase + so * 2u, &g_phi[gp]);
            cp16(ubase + (so + CTX_PH) * 2u, &g_plo[gp]);
        }
        {
            const int row = tid >> 3, dc = tid & 7;  // 32 rows x 8 chunks
            const size_t gv = vbase + (size_t)(k0 + row) * Dd + dc * 8;
            const uint32_t so = bofs + 2 * CTX_PH + row * LDSV + dc * 8;
            cp16(ubase + so * 2u, &g_vhi[gv]);
            cp16(ubase + (so + CTX_VH) * 2u, &g_vlo[gv]);
        }
    };

    stage(0, 0);
    CP_COMMIT();

    const int NKI = Ss / 32;   // 64
    for (int ki = 0; ki < NKI; ki++) {
        if (ki + 1 < NKI) {
            stage(ki + 1, (ki + 1) & 1);
            CP_COMMIT();
            CP_WAIT1();
        } else {
            CP_WAIT0();
        }
        __syncthreads();

        const uint32_t bofs = (uint32_t)(ki & 1) * CTX_BLK;
        const uint32_t uPh = ubase + bofs * 2u;
        const uint32_t uPl = ubase + (bofs + CTX_PH) * 2u;
        const uint32_t uVh = ubase + (bofs + 2 * CTX_PH) * 2u;
        const uint32_t uVl = ubase + (bofs + 2 * CTX_PH + CTX_VH) * 2u;

#pragma unroll
        for (int ks = 0; ks < 32; ks += 16) {
            uint32_t ah[4], al[4], bh2[8][2], bl2[8][2];
            load_a_frag(ah, uPh, wid * 16, ks, lane, LDSA);
            load_a_frag(al, uPl, wid * 16, ks, lane, LDSA);
#pragma unroll
            for (int p = 0; p < 4; p++) {
                load_b_frag2_trans(bh2[2 * p], bh2[2 * p + 1], uVh, p * 16, ks, lane, LDSV);
                load_b_frag2_trans(bl2[2 * p], bl2[2 * p + 1], uVl, p * 16, ks, lane, LDSV);
            }
#pragma unroll
            for (int nt = 0; nt < 8; nt++) {
                mma16816(acc[nt], ah, bh2[nt]);
                mma16816(acc[nt], ah, bl2[nt]);
                mma16816(acc[nt], al, bh2[nt]);
            }
        }
        __syncthreads();
    }

    // epilogue: split ctx into g_chi/g_clo at (b, t, h*64 + d)
#pragma unroll
    for (int nt = 0; nt < 8; nt++) {
        const int d = nt * 8 + 2 * (lane & 3);
#pragma unroll
        for (int half = 0; half < 2; half++) {
            const int t = row0 + wid * 16 + (lane >> 2) + half * 8;
            const size_t o = ((size_t)b * Tt + t) * Ee + h * Dd + d;
            uint32_t hi, lo;
            split2(acc[nt][2 * half], acc[nt][2 * half + 1], hi, lo);
            *reinterpret_cast<uint32_t*>(&g_chi[o]) = hi;
            *reinterpret_cast<uint32_t*>(&g_clo[o]) = lo;
        }
    }
}

// ---------------------------------------------------------------------------
extern "C" void kernel_launch(void* const* d_in, const int* in_sizes, int n_in,
                              void* d_out, int out_size)
{
    const float* q    = (const float*)d_in[0];
    const float* kv   = (const float*)d_in[1];
    const float* ipw  = (const float*)d_in[2];
    const float* ipb  = (const float*)d_in[3];
    const float* opw  = (const float*)d_in[4];
    const float* opb  = (const float*)d_in[5];
    float* out = (float*)d_out;                       // (B,T,H,D) flattened
    float* wout = out + (size_t)Bb * Tt * Ee;         // (B,T,S) flattened

    cudaFuncSetAttribute(proj_mma_kernel,
                         cudaFuncAttributeMaxDynamicSharedMemorySize, PROJ_SMEM);
    cudaFuncSetAttribute(scores_mma_kernel,
                         cudaFuncAttributeMaxDynamicSharedMemorySize, SC_SMEM);
    cudaFuncSetAttribute(ctx_mma_kernel,
                         cudaFuncAttributeMaxDynamicSharedMemorySize, CTX_SMEM);

    // 0. split conversions (weights + activations)
    convert_qkv_kernel<<<dim3(4096, 1, 3), 256>>>(q, kv);
    convert_w_kernel<<<4096, 256>>>(ipw, opw);

    // 1. QKV projections -> split bf16 Q/K/V operands
    proj_mma_kernel<<<dim3(8, 32, 3), 256, PROJ_SMEM>>>(ipb, nullptr, 0);

    // 2. scores -> f32 g_attn (4 col tiles per CTA, pipelined)
    scores_mma_kernel<<<dim3(4, 16, Bb * Hh), 256, SC_SMEM>>>();

    // 3. softmax -> split bf16 probs + head-mean wout
    softmax_kernel<<<Bb * Tt, 256>>>(wout);

    // 4. ctx = P @ V -> split bf16 g_chi/g_clo (pipelined)
    ctx_mma_kernel<<<dim3(1, 16, Bb * Hh), 256, CTX_SMEM>>>();

    // 5. out projection -> f32 d_out
    proj_mma_kernel<<<dim3(8, 32, 1), 256, PROJ_SMEM>>>(opb, out, 3);
}

// round 17
// speedup vs baseline: 3.1093x; 1.0971x over previous
#include <cuda_runtime.h>
#include <cuda_bf16.h>
#include <cstdint>
#include <math.h>

#define Bb 2
#define Tt 2048
#define Ss 2048
#define Hh 16
#define Dd 64
#define Ee 1024

// ---------------------------------------------------------------------------
// Scratch (static __device__). Referenced ONLY from device code — never passed
// as kernel arguments from host (R7/R11 root cause).
// ---------------------------------------------------------------------------
__device__ float g_attn[(size_t)Bb * Hh * Tt * Ss];        // f32 scores (512 MB)

__device__ __nv_bfloat16 g_ahi[(size_t)3 * 4096 * 1024];   // qkv activations split
__device__ __nv_bfloat16 g_alo[(size_t)3 * 4096 * 1024];
__device__ __nv_bfloat16 g_whi[(size_t)4 * 1024 * 1024];   // in_proj(3)+out_proj(1)
__device__ __nv_bfloat16 g_wlo[(size_t)4 * 1024 * 1024];

#define PROJ_ELEMS ((size_t)Bb * Hh * Tt * Dd)
__device__ __nv_bfloat16 g_qhi[PROJ_ELEMS], g_qlo[PROJ_ELEMS];
__device__ __nv_bfloat16 g_khi[PROJ_ELEMS], g_klo[PROJ_ELEMS];
__device__ __nv_bfloat16 g_vhi[PROJ_ELEMS], g_vlo[PROJ_ELEMS];

__device__ __nv_bfloat16 g_phi[(size_t)Bb * Hh * Tt * Ss]; // softmax probs split
__device__ __nv_bfloat16 g_plo[(size_t)Bb * Hh * Tt * Ss];

__device__ __nv_bfloat16 g_chi[(size_t)4096 * 1024];       // ctx split
__device__ __nv_bfloat16 g_clo[(size_t)4096 * 1024];

// ---------------------------------------------------------------------------
// Primitives
// ---------------------------------------------------------------------------
__device__ __forceinline__ uint32_t smem_u32(const void* p) {
    uint32_t a;
    asm("{ .reg .u64 t; cvta.to.shared.u64 t, %1; cvt.u32.u64 %0, t; }"
        : "=r"(a) : "l"(p));
    return a;
}

__device__ __forceinline__ void mma16816(float* d, const uint32_t* a, const uint32_t* b) {
    asm volatile(
        "mma.sync.aligned.m16n8k16.row.col.f32.bf16.bf16.f32 "
        "{%0,%1,%2,%3}, {%4,%5,%6,%7}, {%8,%9}, {%0,%1,%2,%3};"
        : "+f"(d[0]), "+f"(d[1]), "+f"(d[2]), "+f"(d[3])
        : "r"(a[0]), "r"(a[1]), "r"(a[2]), "r"(a[3]), "r"(b[0]), "r"(b[1]));
}

#define LDSM4(R0,R1,R2,R3,ADDR) \
    asm volatile("ldmatrix.sync.aligned.m8n8.x4.shared.b16 {%0,%1,%2,%3}, [%4];" \
        : "=r"(R0),"=r"(R1),"=r"(R2),"=r"(R3) : "r"(ADDR))
#define LDSM4T(R0,R1,R2,R3,ADDR) \
    asm volatile("ldmatrix.sync.aligned.m8n8.x4.trans.shared.b16 {%0,%1,%2,%3}, [%4];" \
        : "=r"(R0),"=r"(R1),"=r"(R2),"=r"(R3) : "r"(ADDR))

__device__ __forceinline__ void load_a_frag(uint32_t* fr, uint32_t base_u32,
                                            int mbase, int ks, int lane, int lds) {
    const int row = mbase + (lane & 15);
    const int col = ks + ((lane >> 4) << 3);
    LDSM4(fr[0], fr[1], fr[2], fr[3], base_u32 + (uint32_t)(row * lds + col) * 2u);
}
__device__ __forceinline__ void load_b_frag2(uint32_t* f0, uint32_t* f1, uint32_t base_u32,
                                             int nb, int ks, int lane, int lds) {
    const int g = lane >> 3, r = lane & 7;
    const int row = nb + ((g >> 1) << 3) + r;
    const int col = ks + ((g & 1) << 3);
    LDSM4(f0[0], f0[1], f1[0], f1[1], base_u32 + (uint32_t)(row * lds + col) * 2u);
}
__device__ __forceinline__ void load_b_frag2_trans(uint32_t* f0, uint32_t* f1, uint32_t base_u32,
                                                   int db, int ks, int lane, int lds) {
    const int g = lane >> 3, r = lane & 7;
    const int row = ks + ((g & 1) << 3) + r;
    const int col = db + ((g >> 1) << 3);
    LDSM4T(f0[0], f0[1], f1[0], f1[1], base_u32 + (uint32_t)(row * lds + col) * 2u);
}

__device__ __forceinline__ void cp16(uint32_t saddr, const void* gptr) {
    asm volatile("cp.async.cg.shared.global [%0], [%1], 16;"
                 :: "r"(saddr), "l"(gptr));
}
#define CP_COMMIT() asm volatile("cp.async.commit_group;" ::: "memory")
#define CP_WAIT1()  asm volatile("cp.async.wait_group 1;" ::: "memory")
#define CP_WAIT0()  asm volatile("cp.async.wait_group 0;" ::: "memory")

__device__ __forceinline__ void split4(float4 v, ushort4& hs, ushort4& ls)
{
    __nv_bfloat16 h0 = __float2bfloat16(v.x);
    __nv_bfloat16 h1 = __float2bfloat16(v.y);
    __nv_bfloat16 h2 = __float2bfloat16(v.z);
    __nv_bfloat16 h3 = __float2bfloat16(v.w);
    __nv_bfloat16 l0 = __float2bfloat16(v.x - __bfloat162float(h0));
    __nv_bfloat16 l1 = __float2bfloat16(v.y - __bfloat162float(h1));
    __nv_bfloat16 l2 = __float2bfloat16(v.z - __bfloat162float(h2));
    __nv_bfloat16 l3 = __float2bfloat16(v.w - __bfloat162float(h3));
    hs = make_ushort4(__bfloat16_as_ushort(h0), __bfloat16_as_ushort(h1),
                      __bfloat16_as_ushort(h2), __bfloat16_as_ushort(h3));
    ls = make_ushort4(__bfloat16_as_ushort(l0), __bfloat16_as_ushort(l1),
                      __bfloat16_as_ushort(l2), __bfloat16_as_ushort(l3));
}
__device__ __forceinline__ void split2(float a, float b, uint32_t& hi, uint32_t& lo) {
    __nv_bfloat16 ha = __float2bfloat16(a), hb = __float2bfloat16(b);
    hi = ((uint32_t)__bfloat16_as_ushort(hb) << 16) | __bfloat16_as_ushort(ha);
    __nv_bfloat16 la = __float2bfloat16(a - __bfloat162float(ha));
    __nv_bfloat16 lb = __float2bfloat16(b - __bfloat162float(hb));
    lo = ((uint32_t)__bfloat16_as_ushort(lb) << 16) | __bfloat16_as_ushort(la);
}

// ---------------------------------------------------------------------------
// Conversion kernels (validated)
// ---------------------------------------------------------------------------
__global__ __launch_bounds__(256)
void convert_qkv_kernel(const float* __restrict__ q, const float* __restrict__ kv)
{
    const int z = blockIdx.z;
    const size_t idx4 = ((size_t)blockIdx.x * 256 + threadIdx.x) * 4;
    const size_t m = idx4 >> 10;
    const size_t e = idx4 & 1023;
    const float* src;
    if (z == 0)      src = q  + m * 1024 + e;
    else if (z == 1) src = kv + m * 2048 + e;
    else             src = kv + m * 2048 + 1024 + e;
    float4 v = *reinterpret_cast<const float4*>(src);
    ushort4 hs, ls;
    split4(v, hs, ls);
    const size_t o = (size_t)z * 4096 * 1024 + idx4;
    *reinterpret_cast<ushort4*>(&g_ahi[o]) = hs;
    *reinterpret_cast<ushort4*>(&g_alo[o]) = ls;
}

__global__ __launch_bounds__(256)
void convert_w_kernel(const float* __restrict__ ipw, const float* __restrict__ opw)
{
    const size_t idx4 = ((size_t)blockIdx.x * 256 + threadIdx.x) * 4;
    const size_t r = idx4 >> 10;
    const size_t e = idx4 & 1023;
    const float* src = (r < 3072) ? (ipw + idx4) : (opw + ((r - 3072) << 10) + e);
    float4 v = *reinterpret_cast<const float4*>(src);
    ushort4 hs, ls;
    split4(v, hs, ls);
    *reinterpret_cast<ushort4*>(&g_whi[idx4]) = hs;
    *reinterpret_cast<ushort4*>(&g_wlo[idx4]) = ls;
}

// ---------------------------------------------------------------------------
// proj GEMM (HMMA 3xBF16): k-tile 32, 80KB smem, 2 CTAs/SM.
// ---------------------------------------------------------------------------
#define KT 32
#define LDP_P 40
#define PTILE_HALFS (128 * LDP_P)            // 5120
#define PROJ_SMEM (2 * 4 * PTILE_HALFS * 2)  // 81920 B

__global__ __launch_bounds__(256, 2)
void proj_mma_kernel(const float* __restrict__ biasBase,
                     float* __restrict__ outPlain,
                     int outmode)
{
    extern __shared__ __nv_bfloat16 dynsm[];
    const uint32_t ubase = smem_u32(dynsm);

    const int tid = threadIdx.x;
    const int lane = tid & 31, wid = tid >> 5;
    const int wm = wid >> 1, wn = wid & 1;
    const int z = (outmode == 3) ? 3 : blockIdx.z;

    const __nv_bfloat16 *Ah, *Al;
    if (outmode == 3) { Ah = g_chi; Al = g_clo; }
    else {
        Ah = g_ahi + (size_t)z * 4096 * 1024;
        Al = g_alo + (size_t)z * 4096 * 1024;
    }
    const __nv_bfloat16* Wh = g_whi + (size_t)z * 1024 * 1024;
    const __nv_bfloat16* Wl = g_wlo + (size_t)z * 1024 * 1024;
    const float* bias = biasBase + (outmode == 3 ? 0 : z * 1024);

    const int row0 = blockIdx.y * 128;
    const int col0 = blockIdx.x * 128;

    const __nv_bfloat16* gbase[4] = {
        Ah + (size_t)row0 * 1024, Al + (size_t)row0 * 1024,
        Wh + (size_t)col0 * 1024, Wl + (size_t)col0 * 1024
    };

    float acc[2][8][4];
#pragma unroll
    for (int i = 0; i < 2; i++)
#pragma unroll
        for (int j = 0; j < 8; j++)
#pragma unroll
            for (int k = 0; k < 4; k++) acc[i][j][k] = 0.0f;

    // stage kt into buffer buf: 4 ops x 128 rows x 4 chunks = 2048 cp.async
    auto stage = [&](int kt, int buf) {
#pragma unroll
        for (int i = 0; i < 8; i++) {
            const int idx = tid + i * 256;         // 0..2047
            const int op = idx >> 9;
            const int c = idx & 511;
            const int row = c >> 2, kc = c & 3;
            const __nv_bfloat16* src = gbase[op] + (size_t)row * 1024 + kt * KT + kc * 8;
            const uint32_t dst = ubase +
                ((uint32_t)(buf * 4 + op) * PTILE_HALFS + row * LDP_P + kc * 8) * 2u;
            cp16(dst, src);
        }
    };

    stage(0, 0);
    CP_COMMIT();

    const int NKT = 1024 / KT;   // 32
    for (int kt = 0; kt < NKT; kt++) {
        if (kt + 1 < NKT) {
            stage(kt + 1, (kt + 1) & 1);
            CP_COMMIT();
            CP_WAIT1();
        } else {
            CP_WAIT0();
        }
        __syncthreads();

        const int buf = kt & 1;
        const uint32_t uAh = ubase + (uint32_t)(buf * 4 + 0) * PTILE_HALFS * 2u;
        const uint32_t uAl = ubase + (uint32_t)(buf * 4 + 1) * PTILE_HALFS * 2u;
        const uint32_t uBh = ubase + (uint32_t)(buf * 4 + 2) * PTILE_HALFS * 2u;
        const uint32_t uBl = ubase + (uint32_t)(buf * 4 + 3) * PTILE_HALFS * 2u;

#pragma unroll
        for (int ks = 0; ks < KT; ks += 16) {
            uint32_t ah[2][4], al[2][4], bh2[8][2], bl2[8][2];
#pragma unroll
            for (int mt = 0; mt < 2; mt++) {
                load_a_frag(ah[mt], uAh, wm * 32 + mt * 16, ks, lane, LDP_P);
                load_a_frag(al[mt], uAl, wm * 32 + mt * 16, ks, lane, LDP_P);
            }
#pragma unroll
            for (int p = 0; p < 4; p++) {
                load_b_frag2(bh2[2 * p], bh2[2 * p + 1], uBh, wn * 64 + p * 16, ks, lane, LDP_P);
                load_b_frag2(bl2[2 * p], bl2[2 * p + 1], uBl, wn * 64 + p * 16, ks, lane, LDP_P);
            }
#pragma unroll
            for (int mt = 0; mt < 2; mt++)
#pragma unroll
                for (int nt = 0; nt < 8; nt++) {
                    mma16816(acc[mt][nt], ah[mt], bh2[nt]);
                    mma16816(acc[mt][nt], ah[mt], bl2[nt]);
                    mma16816(acc[mt][nt], al[mt], bh2[nt]);
                }
        }
        __syncthreads();
    }

    __nv_bfloat16* dsthi = (z == 0) ? g_qhi : (z == 1) ? g_khi : g_vhi;
    __nv_bfloat16* dstlo = (z == 0) ? g_qlo : (z == 1) ? g_klo : g_vlo;
#pragma unroll
    for (int mt = 0; mt < 2; mt++) {
#pragma unroll
        for (int nt = 0; nt < 8; nt++) {
            const int n = col0 + wn * 64 + nt * 8 + 2 * (lane & 3);
            const float b0 = bias[n], b1 = bias[n + 1];
#pragma unroll
            for (int half = 0; half < 2; half++) {
                const int m = row0 + wm * 32 + mt * 16 + (lane >> 2) + half * 8;
                const float v0 = acc[mt][nt][2 * half + 0] + b0;
                const float v1 = acc[mt][nt][2 * half + 1] + b1;
                if (outmode == 3) {
                    *reinterpret_cast<float2*>(&outPlain[(size_t)m * Ee + n]) =
                        make_float2(v0, v1);
                } else {
                    const int bidx = m >> 11, t = m & 2047;
                    const int h = n >> 6, d = n & 63;
                    const size_t o = (((size_t)bidx * Hh + h) * Tt + t) * Dd + d;
                    uint32_t hi, lo;
                    split2(v0, v1, hi, lo);
                    *reinterpret_cast<uint32_t*>(&dsthi[o]) = hi;
                    *reinterpret_cast<uint32_t*>(&dstlo[o]) = lo;
                }
            }
        }
    }
}

// ---------------------------------------------------------------------------
// scores v2 (HMMA 3xBF16): Q row-tile staged once, 4 K col tiles pipelined.
// 110KB smem + 128-reg cap -> 2 CTAs/SM.
// ---------------------------------------------------------------------------
#define LDP 72
#define SC_TILE (128 * LDP)              // 9216 halfs
#define SC_SMEM ((2 + 4) * SC_TILE * 2)  // 110592 B

__global__ __launch_bounds__(256, 2)
void scores_mma_kernel()
{
    extern __shared__ __nv_bfloat16 dynsm[];
    const uint32_t ubase = smem_u32(dynsm);

    const int tid = threadIdx.x;
    const int lane = tid & 31, wid = tid >> 5;
    const int wm = wid >> 1, wn = wid & 1;
    const int bh = blockIdx.z;
    const size_t base = (size_t)bh * Tt * Dd;
    const int row0 = blockIdx.y * 128;
    const int colg = blockIdx.x * 4;

    {
        const __nv_bfloat16* qsrc[2] = { g_qhi + base + (size_t)row0 * 64,
                                         g_qlo + base + (size_t)row0 * 64 };
#pragma unroll
        for (int i = 0; i < 8; i++) {
            const int idx = tid + i * 256;
            const int op = idx >> 10;
            const int c = idx & 1023;
            const int row = c >> 3, kc = c & 7;
            cp16(ubase + ((uint32_t)op * SC_TILE + row * LDP + kc * 8) * 2u,
                 qsrc[op] + (size_t)row * 64 + kc * 8);
        }
    }
    auto stage_k = [&](int ct, int b) {
        const int col0 = (colg + ct) * 128;
        const __nv_bfloat16* ksrc[2] = { g_khi + base + (size_t)col0 * 64,
                                         g_klo + base + (size_t)col0 * 64 };
#pragma unroll
        for (int i = 0; i < 8; i++) {
            const int idx = tid + i * 256;
            const int op = idx >> 10;
            const int c = idx & 1023;
            const int row = c >> 3, kc = c & 7;
            cp16(ubase + ((uint32_t)(2 + b * 2 + op) * SC_TILE + row * LDP + kc * 8) * 2u,
                 ksrc[op] + (size_t)row * 64 + kc * 8);
        }
    };

    stage_k(0, 0);
    CP_COMMIT();

    const uint32_t uQh = ubase;
    const uint32_t uQl = ubase + (uint32_t)SC_TILE * 2u;

    for (int ct = 0; ct < 4; ct++) {
        if (ct < 3) {
            stage_k(ct + 1, (ct + 1) & 1);
            CP_COMMIT();
            CP_WAIT1();
        } else {
            CP_WAIT0();
        }
        __syncthreads();

        const int buf = ct & 1;
        const uint32_t uKh = ubase + (uint32_t)(2 + buf * 2) * SC_TILE * 2u;
        const uint32_t uKl = uKh + (uint32_t)SC_TILE * 2u;

        float acc[2][8][4];
#pragma unroll
        for (int i = 0; i < 2; i++)
#pragma unroll
            for (int j = 0; j < 8; j++)
#pragma unroll
                for (int k = 0; k < 4; k++) acc[i][j][k] = 0.0f;

#pragma unroll
        for (int ks = 0; ks < 64; ks += 16) {
            uint32_t ah[2][4], al[2][4], bh2[8][2], bl2[8][2];
#pragma unroll
            for (int mt = 0; mt < 2; mt++) {
                load_a_frag(ah[mt], uQh, wm * 32 + mt * 16, ks, lane, LDP);
                load_a_frag(al[mt], uQl, wm * 32 + mt * 16, ks, lane, LDP);
            }
#pragma unroll
            for (int p = 0; p < 4; p++) {
                load_b_frag2(bh2[2 * p], bh2[2 * p + 1], uKh, wn * 64 + p * 16, ks, lane, LDP);
                load_b_frag2(bl2[2 * p], bl2[2 * p + 1], uKl, wn * 64 + p * 16, ks, lane, LDP);
            }
#pragma unroll
            for (int mt = 0; mt < 2; mt++)
#pragma unroll
                for (int nt = 0; nt < 8; nt++) {
                    mma16816(acc[mt][nt], ah[mt], bh2[nt]);
                    mma16816(acc[mt][nt], ah[mt], bl2[nt]);
                    mma16816(acc[mt][nt], al[mt], bh2[nt]);
                }
        }

        float* C = g_attn + (size_t)bh * Tt * Ss;
        const int col0 = (colg + ct) * 128;
#pragma unroll
        for (int mt = 0; mt < 2; mt++)
#pragma unroll
            for (int nt = 0; nt < 8; nt++) {
                const int n = col0 + wn * 64 + nt * 8 + 2 * (lane & 3);
#pragma unroll
                for (int half = 0; half < 2; half++) {
                    const int m = row0 + wm * 32 + mt * 16 + (lane >> 2) + half * 8;
                    *reinterpret_cast<float2*>(&C[(size_t)m * Ss + n]) =
                        make_float2(acc[mt][nt][2 * half] * 0.125f,
                                    acc[mt][nt][2 * half + 1] * 0.125f);
                }
            }
        __syncthreads();
    }
}

// ---------------------------------------------------------------------------
// softmax: shuffle-based reductions (2 syncs/head instead of 16)
// ---------------------------------------------------------------------------
__global__ __launch_bounds__(256)
void softmax_kernel(float* __restrict__ wout)
{
    const int bt = blockIdx.x;
    const int b = bt / Tt, t = bt % Tt;
    const int tid = threadIdx.x;
    const int lane = tid & 31, warp = tid >> 5;

    __shared__ float red[8];

    float wsum[8];
#pragma unroll
    for (int i = 0; i < 8; i++) wsum[i] = 0.0f;

    for (int h = 0; h < Hh; h++) {
        const size_t rowoff = (((size_t)b * Hh + h) * Tt + t) * Ss;
        const float* arow = g_attn + rowoff;
        float lv[8];
        float lmax = -1e30f;
#pragma unroll
        for (int i = 0; i < 8; i++) {
            lv[i] = arow[tid + i * 256];
            lmax = fmaxf(lmax, lv[i]);
        }
#pragma unroll
        for (int o = 16; o > 0; o >>= 1)
            lmax = fmaxf(lmax, __shfl_xor_sync(0xFFFFFFFFu, lmax, o));
        if (lane == 0) red[warp] = lmax;
        __syncthreads();
        {
            float v = red[lane & 7];
#pragma unroll
            for (int o = 4; o > 0; o >>= 1)
                v = fmaxf(v, __shfl_xor_sync(0xFFFFFFFFu, v, o));
            lmax = v;   // all lanes now hold block max
        }
        const float m = lmax;

        float lsum = 0.0f;
#pragma unroll
        for (int i = 0; i < 8; i++) {
            lv[i] = __expf(lv[i] - m);
            lsum += lv[i];
        }
#pragma unroll
        for (int o = 16; o > 0; o >>= 1)
            lsum += __shfl_xor_sync(0xFFFFFFFFu, lsum, o);
        __syncthreads();   // red reuse guard
        if (lane == 0) red[warp] = lsum;
        __syncthreads();
        {
            float v = red[lane & 7];
#pragma unroll
            for (int o = 4; o > 0; o >>= 1)
                v += __shfl_xor_sync(0xFFFFFFFFu, v, o);
            lsum = v;
        }
        const float inv = 1.0f / lsum;

#pragma unroll
        for (int i = 0; i < 8; i++) {
            const float p = lv[i] * inv;
            const __nv_bfloat16 ph = __float2bfloat16(p);
            const __nv_bfloat16 pl = __float2bfloat16(p - __bfloat162float(ph));
            g_phi[rowoff + tid + i * 256] = ph;
            g_plo[rowoff + tid + i * 256] = pl;
            wsum[i] += p * (1.0f / Hh);
        }
        __syncthreads();   // red reuse guard for next head
    }
#pragma unroll
    for (int i = 0; i < 8; i++)
        wout[(size_t)bt * Ss + tid + i * 256] = wsum[i];
}

// ---------------------------------------------------------------------------
// ctx v2 (HMMA 3xBF16): cp.async double-buffered; 2 CTAs/SM.
// ---------------------------------------------------------------------------
#define LDSA 40
#define LDSV 72
#define CTX_PH  (128 * LDSA)
#define CTX_VH  (32 * LDSV)
#define CTX_BLK (2 * CTX_PH + 2 * CTX_VH)
#define CTX_SMEM (2 * CTX_BLK * 2)

__global__ __launch_bounds__(256, 2)
void ctx_mma_kernel()
{
    extern __shared__ __nv_bfloat16 dynsm[];
    const uint32_t ubase = smem_u32(dynsm);

    const int tid = threadIdx.x;
    const int lane = tid & 31, wid = tid >> 5;
    const int bh = blockIdx.z;
    const int b = bh >> 4, h = bh & 15;
    const int row0 = blockIdx.y * 128;
    const size_t pbase = (size_t)bh * Tt * Ss;
    const size_t vbase = (size_t)bh * Ss * Dd;

    float acc[8][4];
#pragma unroll
    for (int j = 0; j < 8; j++)
#pragma unroll
        for (int k = 0; k < 4; k++) acc[j][k] = 0.0f;

    auto stage = [&](int ki, int buf) {
        const int k0 = ki * 32;
        const uint32_t bofs = (uint32_t)buf * CTX_BLK;
#pragma unroll
        for (int c = 0; c < 2; c++) {
            const int ch = tid + c * 256;
            const int row = ch >> 2, kc = ch & 3;
            const size_t gp = pbase + (size_t)(row0 + row) * Ss + k0 + kc * 8;
            const uint32_t so = bofs + row * LDSA + kc * 8;
            cp16(ubase + so * 2u, &g_phi[gp]);
            cp16(ubase + (so + CTX_PH) * 2u, &g_plo[gp]);
        }
        {
            const int row = tid >> 3, dc = tid & 7;
            const size_t gv = vbase + (size_t)(k0 + row) * Dd + dc * 8;
            const uint32_t so = bofs + 2 * CTX_PH + row * LDSV + dc * 8;
            cp16(ubase + so * 2u, &g_vhi[gv]);
            cp16(ubase + (so + CTX_VH) * 2u, &g_vlo[gv]);
        }
    };

    stage(0, 0);
    CP_COMMIT();

    const int NKI = Ss / 32;
    for (int ki = 0; ki < NKI; ki++) {
        if (ki + 1 < NKI) {
            stage(ki + 1, (ki + 1) & 1);
            CP_COMMIT();
            CP_WAIT1();
        } else {
            CP_WAIT0();
        }
        __syncthreads();

        const uint32_t bofs = (uint32_t)(ki & 1) * CTX_BLK;
        const uint32_t uPh = ubase + bofs * 2u;
        const uint32_t uPl = ubase + (bofs + CTX_PH) * 2u;
        const uint32_t uVh = ubase + (bofs + 2 * CTX_PH) * 2u;
        const uint32_t uVl = ubase + (bofs + 2 * CTX_PH + CTX_VH) * 2u;

#pragma unroll
        for (int ks = 0; ks < 32; ks += 16) {
            uint32_t ah[4], al[4], bh2[8][2], bl2[8][2];
            load_a_frag(ah, uPh, wid * 16, ks, lane, LDSA);
            load_a_frag(al, uPl, wid * 16, ks, lane, LDSA);
#pragma unroll
            for (int p = 0; p < 4; p++) {
                load_b_frag2_trans(bh2[2 * p], bh2[2 * p + 1], uVh, p * 16, ks, lane, LDSV);
                load_b_frag2_trans(bl2[2 * p], bl2[2 * p + 1], uVl, p * 16, ks, lane, LDSV);
            }
#pragma unroll
            for (int nt = 0; nt < 8; nt++) {
                mma16816(acc[nt], ah, bh2[nt]);
                mma16816(acc[nt], ah, bl2[nt]);
                mma16816(acc[nt], al, bh2[nt]);
            }
        }
        __syncthreads();
    }

#pragma unroll
    for (int nt = 0; nt < 8; nt++) {
        const int d = nt * 8 + 2 * (lane & 3);
#pragma unroll
        for (int half = 0; half < 2; half++) {
            const int t = row0 + wid * 16 + (lane >> 2) + half * 8;
            const size_t o = ((size_t)b * Tt + t) * Ee + h * Dd + d;
            uint32_t hi, lo;
            split2(acc[nt][2 * half], acc[nt][2 * half + 1], hi, lo);
            *reinterpret_cast<uint32_t*>(&g_chi[o]) = hi;
            *reinterpret_cast<uint32_t*>(&g_clo[o]) = lo;
        }
    }
}

// ---------------------------------------------------------------------------
extern "C" void kernel_launch(void* const* d_in, const int* in_sizes, int n_in,
                              void* d_out, int out_size)
{
    const float* q    = (const float*)d_in[0];
    const float* kv   = (const float*)d_in[1];
    const float* ipw  = (const float*)d_in[2];
    const float* ipb  = (const float*)d_in[3];
    const float* opw  = (const float*)d_in[4];
    const float* opb  = (const float*)d_in[5];
    float* out = (float*)d_out;                       // (B,T,H,D) flattened
    float* wout = out + (size_t)Bb * Tt * Ee;         // (B,T,S) flattened

    cudaFuncSetAttribute(proj_mma_kernel,
                         cudaFuncAttributeMaxDynamicSharedMemorySize, PROJ_SMEM);
    cudaFuncSetAttribute(scores_mma_kernel,
                         cudaFuncAttributeMaxDynamicSharedMemorySize, SC_SMEM);
    cudaFuncSetAttribute(ctx_mma_kernel,
                         cudaFuncAttributeMaxDynamicSharedMemorySize, CTX_SMEM);

    // 0. split conversions (weights + activations)
    convert_qkv_kernel<<<dim3(4096, 1, 3), 256>>>(q, kv);
    convert_w_kernel<<<4096, 256>>>(ipw, opw);

    // 1. QKV projections -> split bf16 Q/K/V operands
    proj_mma_kernel<<<dim3(8, 32, 3), 256, PROJ_SMEM>>>(ipb, nullptr, 0);

    // 2. scores -> f32 g_attn (4 col tiles per CTA, pipelined)
    scores_mma_kernel<<<dim3(4, 16, Bb * Hh), 256, SC_SMEM>>>();

    // 3. softmax -> split bf16 probs + head-mean wout
    softmax_kernel<<<Bb * Tt, 256>>>(wout);

    // 4. ctx = P @ V -> split bf16 g_chi/g_clo (pipelined)
    ctx_mma_kernel<<<dim3(1, 16, Bb * Hh), 256, CTX_SMEM>>>();

    // 5. out projection -> f32 d_out
    proj_mma_kernel<<<dim3(8, 32, 1), 256, PROJ_SMEM>>>(opb, out, 3);
}